// round 1
// baseline (speedup 1.0000x reference)
#include <cuda_runtime.h>
#include <math.h>

#define S_    2048
#define HID_  2048
#define H_    16
#define D_    256
#define NOPE_ 192
#define RH_   32      // R/2
#define QL_   1024
#define OR_   512
#define G_    4
#define EPS_  1e-6f
#define SCALE_ 0.0625f   // 256^-0.5

// -------- scratch (no allocations allowed) --------
__device__ float g_qa[S_ * QL_];                 // 8 MB
__device__ float g_q[(size_t)S_ * H_ * D_];      // 32 MB
__device__ float g_kv[S_ * D_];                  // 2 MB
__device__ float g_o[(size_t)S_ * H_ * D_];      // 32 MB
__device__ float g_or[S_ * G_ * OR_];            // 16 MB

// ==================== generic GEMM: C[M,N] = A[M,K] * B[N,K]^T ====================
// 64x64 tile, BK=16, 256 threads, 4x4 register tile. M,N multiples of 64, K of 16.
__global__ void __launch_bounds__(256) gemm_abt(
    const float* __restrict__ A, int lda,
    const float* __restrict__ B, int ldb,
    float* __restrict__ C, int ldc, int K)
{
    __shared__ float As[16][68];
    __shared__ float Bs[16][68];
    const int tid = threadIdx.x;
    const int tx = tid & 15, ty = tid >> 4;
    const int lr = tid >> 2, lq = tid & 3;
    const float* Ab = A + (size_t)(blockIdx.x * 64 + lr) * lda + lq * 4;
    const float* Bb = B + (size_t)(blockIdx.y * 64 + lr) * ldb + lq * 4;
    float acc[4][4] = {};
    for (int k0 = 0; k0 < K; k0 += 16) {
        float4 av = *(const float4*)(Ab + k0);
        float4 bv = *(const float4*)(Bb + k0);
        As[lq*4+0][lr] = av.x; As[lq*4+1][lr] = av.y;
        As[lq*4+2][lr] = av.z; As[lq*4+3][lr] = av.w;
        Bs[lq*4+0][lr] = bv.x; Bs[lq*4+1][lr] = bv.y;
        Bs[lq*4+2][lr] = bv.z; Bs[lq*4+3][lr] = bv.w;
        __syncthreads();
        #pragma unroll
        for (int k = 0; k < 16; k++) {
            float4 a = *(const float4*)&As[k][ty * 4];
            float4 b = *(const float4*)&Bs[k][tx * 4];
            float ar[4] = {a.x, a.y, a.z, a.w};
            float br[4] = {b.x, b.y, b.z, b.w};
            #pragma unroll
            for (int i = 0; i < 4; i++)
                #pragma unroll
                for (int j = 0; j < 4; j++)
                    acc[i][j] += ar[i] * br[j];
        }
        __syncthreads();
    }
    float* Cp = C + (size_t)(blockIdx.x * 64 + ty * 4) * ldc + blockIdx.y * 64 + tx * 4;
    #pragma unroll
    for (int i = 0; i < 4; i++) {
        float4 v = make_float4(acc[i][0], acc[i][1], acc[i][2], acc[i][3]);
        *(float4*)(Cp + (size_t)i * ldc) = v;
    }
}

// ==================== RMS norm over rows of length L (with weight) ====================
__global__ void rmsnorm_rows(float* __restrict__ x, const float* __restrict__ w, int L)
{
    int row = blockIdx.x;
    float* p = x + (size_t)row * L;
    float ss = 0.f;
    for (int i = threadIdx.x; i < L; i += blockDim.x) { float v = p[i]; ss += v * v; }
    __shared__ float red[8];
    #pragma unroll
    for (int o = 16; o; o >>= 1) ss += __shfl_xor_sync(0xffffffffu, ss, o);
    if ((threadIdx.x & 31) == 0) red[threadIdx.x >> 5] = ss;
    __syncthreads();
    if (threadIdx.x < 32) {
        float v = (threadIdx.x < 8) ? red[threadIdx.x] : 0.f;
        #pragma unroll
        for (int o = 4; o; o >>= 1) v += __shfl_xor_sync(0xffffffffu, v, o);
        if (threadIdx.x == 0) red[0] = v;
    }
    __syncthreads();
    float inv = rsqrtf(red[0] / (float)L + EPS_);
    for (int i = threadIdx.x; i < L; i += blockDim.x) p[i] = p[i] * inv * w[i];
}

// ==================== q prep: per-(s,h) head-norm (no weight) + RoPE on last 64 ====================
__global__ void qprep(float* __restrict__ q, const float* __restrict__ freqs)
{
    int s = blockIdx.x, h = blockIdx.y;
    float* p = q + ((size_t)s * H_ + h) * D_;
    int t = threadIdx.x;  // 256
    float v = p[t];
    float ss = v * v;
    __shared__ float red[8];
    __shared__ float rowbuf[D_];
    #pragma unroll
    for (int o = 16; o; o >>= 1) ss += __shfl_xor_sync(0xffffffffu, ss, o);
    if ((t & 31) == 0) red[t >> 5] = ss;
    __syncthreads();
    if (t < 32) {
        float r = (t < 8) ? red[t] : 0.f;
        #pragma unroll
        for (int o = 4; o; o >>= 1) r += __shfl_xor_sync(0xffffffffu, r, o);
        if (t == 0) red[0] = r;
    }
    __syncthreads();
    float inv = rsqrtf(red[0] / (float)D_ + EPS_);
    v *= inv;
    rowbuf[t] = v;
    __syncthreads();
    float outv = v;
    if (t >= NOPE_) {
        int i = (t - NOPE_) >> 1;
        float f = freqs[s * RH_ + i];
        float c = cosf(f), sn = sinf(f);
        float x1 = rowbuf[NOPE_ + 2 * i], x2 = rowbuf[NOPE_ + 2 * i + 1];
        outv = ((t & 1) == 0) ? (x1 * c - x2 * sn) : (x1 * sn + x2 * c);
    }
    p[t] = outv;
}

// ==================== kv prep: rms(with weight) + RoPE on last 64 ====================
__global__ void kvprep(float* __restrict__ kv, const float* __restrict__ w,
                       const float* __restrict__ freqs)
{
    int s = blockIdx.x;
    float* p = kv + (size_t)s * D_;
    int t = threadIdx.x;  // 256
    float v = p[t];
    float ss = v * v;
    __shared__ float red[8];
    __shared__ float rowbuf[D_];
    #pragma unroll
    for (int o = 16; o; o >>= 1) ss += __shfl_xor_sync(0xffffffffu, ss, o);
    if ((t & 31) == 0) red[t >> 5] = ss;
    __syncthreads();
    if (t < 32) {
        float r = (t < 8) ? red[t] : 0.f;
        #pragma unroll
        for (int o = 4; o; o >>= 1) r += __shfl_xor_sync(0xffffffffu, r, o);
        if (t == 0) red[0] = r;
    }
    __syncthreads();
    float inv = rsqrtf(red[0] / (float)D_ + EPS_);
    v = v * inv * w[t];
    rowbuf[t] = v;
    __syncthreads();
    float outv = v;
    if (t >= NOPE_) {
        int i = (t - NOPE_) >> 1;
        float f = freqs[s * RH_ + i];
        float c = cosf(f), sn = sinf(f);
        float x1 = rowbuf[NOPE_ + 2 * i], x2 = rowbuf[NOPE_ + 2 * i + 1];
        outv = ((t & 1) == 0) ? (x1 * c - x2 * sn) : (x1 * sn + x2 * c);
    }
    p[t] = outv;
}

// ==================== causal flash attention with sink; K == V == kv (256-dim) ====================
// grid (S/32, H), 256 threads. Thread (ty,tx): row s0+ty, o columns tx*4 + 32*g.
__global__ void __launch_bounds__(256) attn_kernel(
    const float* __restrict__ q, const float* __restrict__ kv,
    const float* __restrict__ sink, float* __restrict__ o)
{
    __shared__ float kv_s[32 * 256];  // 32 KB
    int qb = blockIdx.x, h = blockIdx.y;
    int s0 = qb * 32;
    int tid = threadIdx.x;
    int ty = tid >> 3, tx = tid & 7;
    int srow = s0 + ty;
    const float* qp = q + ((size_t)srow * H_ + h) * D_;
    float4 qv[8];
    #pragma unroll
    for (int g = 0; g < 8; g++) qv[g] = *(const float4*)(qp + tx * 4 + 32 * g);
    float4 oa[8];
    #pragma unroll
    for (int g = 0; g < 8; g++) oa[g] = make_float4(0.f, 0.f, 0.f, 0.f);
    float m = -1e30f, l = 0.f;
    int ntiles = qb + 1;
    for (int t0 = 0; t0 < ntiles; t0++) {
        __syncthreads();
        for (int i = tid; i < 32 * 64; i += 256) {
            int r = i >> 6, c4 = i & 63;
            *(float4*)&kv_s[r * 256 + c4 * 4] =
                *(const float4*)&kv[(size_t)(t0 * 32 + r) * D_ + c4 * 4];
        }
        __syncthreads();
        float sc[4];
        #pragma unroll
        for (int t = 0; t < 32; t++) {
            float part = 0.f;
            #pragma unroll
            for (int g = 0; g < 8; g++) {
                float4 kvv = *(const float4*)&kv_s[t * 256 + tx * 4 + 32 * g];
                part += qv[g].x * kvv.x + qv[g].y * kvv.y
                      + qv[g].z * kvv.z + qv[g].w * kvv.w;
            }
            part += __shfl_xor_sync(0xffffffffu, part, 1, 8);
            part += __shfl_xor_sync(0xffffffffu, part, 2, 8);
            part += __shfl_xor_sync(0xffffffffu, part, 4, 8);
            if ((t & 7) == tx) sc[t >> 3] = part;
        }
        float tmax = -1e30f;
        #pragma unroll
        for (int i = 0; i < 4; i++) {
            int kt = t0 * 32 + i * 8 + tx;
            float v = sc[i] * SCALE_;
            if (kt > srow) v = -1e30f;
            sc[i] = v;
            tmax = fmaxf(tmax, v);
        }
        tmax = fmaxf(tmax, __shfl_xor_sync(0xffffffffu, tmax, 1, 8));
        tmax = fmaxf(tmax, __shfl_xor_sync(0xffffffffu, tmax, 2, 8));
        tmax = fmaxf(tmax, __shfl_xor_sync(0xffffffffu, tmax, 4, 8));
        float mnew = fmaxf(m, tmax);
        float alpha = __expf(m - mnew);
        float psum = 0.f;
        #pragma unroll
        for (int i = 0; i < 4; i++) { sc[i] = __expf(sc[i] - mnew); psum += sc[i]; }
        psum += __shfl_xor_sync(0xffffffffu, psum, 1, 8);
        psum += __shfl_xor_sync(0xffffffffu, psum, 2, 8);
        psum += __shfl_xor_sync(0xffffffffu, psum, 4, 8);
        l = l * alpha + psum;
        m = mnew;
        #pragma unroll
        for (int g = 0; g < 8; g++) {
            oa[g].x *= alpha; oa[g].y *= alpha; oa[g].z *= alpha; oa[g].w *= alpha;
        }
        #pragma unroll
        for (int i = 0; i < 4; i++) {
            #pragma unroll
            for (int u = 0; u < 8; u++) {
                float pv = __shfl_sync(0xffffffffu, sc[i], u, 8);
                int t = i * 8 + u;
                #pragma unroll
                for (int g = 0; g < 8; g++) {
                    float4 kvv = *(const float4*)&kv_s[t * 256 + tx * 4 + 32 * g];
                    oa[g].x += pv * kvv.x; oa[g].y += pv * kvv.y;
                    oa[g].z += pv * kvv.z; oa[g].w += pv * kvv.w;
                }
            }
        }
    }
    l += __expf(sink[h] - m);
    float inv = 1.f / l;
    float* op = o + ((size_t)srow * H_ + h) * D_;
    #pragma unroll
    for (int g = 0; g < 8; g++) {
        float4 v = make_float4(oa[g].x * inv, oa[g].y * inv, oa[g].z * inv, oa[g].w * inv);
        *(float4*)(op + tx * 4 + 32 * g) = v;
    }
}

// ==================== conjugate RoPE on o's last 64 dims ====================
__global__ void o_rope_conj(float* __restrict__ o, const float* __restrict__ freqs)
{
    int s = blockIdx.x, h = blockIdx.y;
    int i = threadIdx.x;  // 32
    float* p = o + ((size_t)s * H_ + h) * D_ + NOPE_;
    float f = freqs[s * RH_ + i];
    float c = cosf(f), sn = sinf(f);
    float x1 = p[2 * i], x2 = p[2 * i + 1];
    p[2 * i]     = x1 * c + x2 * sn;
    p[2 * i + 1] = x2 * c - x1 * sn;
}

// ==================== launch ====================
extern "C" void kernel_launch(void* const* d_in, const int* in_sizes, int n_in,
                              void* d_out, int out_size)
{
    const float* x         = (const float*)d_in[0];
    const float* freqs     = (const float*)d_in[1];
    const float* wq_a      = (const float*)d_in[2];
    const float* q_norm_w  = (const float*)d_in[3];
    const float* wq_b      = (const float*)d_in[4];
    const float* wkv       = (const float*)d_in[5];
    const float* kv_norm_w = (const float*)d_in[6];
    const float* wo_a_w    = (const float*)d_in[7];
    const float* wo_b      = (const float*)d_in[8];
    const float* attn_sink = (const float*)d_in[9];
    float* out = (float*)d_out;

    float *qa, *qbuf, *kvbuf, *obuf, *orbuf;
    cudaGetSymbolAddress((void**)&qa,    g_qa);
    cudaGetSymbolAddress((void**)&qbuf,  g_q);
    cudaGetSymbolAddress((void**)&kvbuf, g_kv);
    cudaGetSymbolAddress((void**)&obuf,  g_o);
    cudaGetSymbolAddress((void**)&orbuf, g_or);

    dim3 blk(256);
    // q_a = x @ wq_a^T    [2048,1024]
    gemm_abt<<<dim3(32, 16), blk>>>(x, HID_, wq_a, HID_, qa, QL_, HID_);
    // kv_raw = x @ wkv^T  [2048,256]
    gemm_abt<<<dim3(32, 4), blk>>>(x, HID_, wkv, HID_, kvbuf, D_, HID_);
    // rms(q_a)
    rmsnorm_rows<<<S_, 256>>>(qa, q_norm_w, QL_);
    // q = q_a @ wq_b^T    [2048,4096]
    gemm_abt<<<dim3(32, 64), blk>>>(qa, QL_, wq_b, QL_, qbuf, H_ * D_, QL_);
    // kv: rms + rope
    kvprep<<<S_, 256>>>(kvbuf, kv_norm_w, freqs);
    // q: head-norm + rope
    qprep<<<dim3(S_, H_), 256>>>(qbuf, freqs);
    // attention
    attn_kernel<<<dim3(S_ / 32, H_), 256>>>(qbuf, kvbuf, attn_sink, obuf);
    // conj rope on o
    o_rope_conj<<<dim3(S_, H_), 32>>>(obuf, freqs);
    // grouped low-rank: o_r[:, g*512:(g+1)*512] = o[:, g*1024:(g+1)*1024] @ wo_a_w[g]^T
    for (int g = 0; g < G_; g++)
        gemm_abt<<<dim3(32, 8), blk>>>(obuf + g * 1024, H_ * D_,
                                       wo_a_w + (size_t)g * OR_ * 1024, 1024,
                                       orbuf + g * OR_, G_ * OR_, 1024);
    // out = o_r @ wo_b^T  [2048,2048]
    gemm_abt<<<dim3(32, 32), blk>>>(orbuf, G_ * OR_, wo_b, HID_, out, HID_, G_ * OR_);
}

// round 2
// speedup vs baseline: 4.6712x; 4.6712x over previous
#include <cuda_runtime.h>
#include <math.h>

#define S_    2048
#define HID_  2048
#define H_    16
#define D_    256
#define NOPE_ 192
#define RH_   32      // R/2
#define QL_   1024
#define OR_   512
#define G_    4
#define EPS_  1e-6f
#define SCALE_ 0.0625f   // 256^-0.5

// -------- scratch (no allocations allowed) --------
__device__ float g_qa[S_ * QL_];                 // 8 MB
__device__ float g_q[(size_t)S_ * H_ * D_];      // 32 MB
__device__ float g_kv[S_ * D_];                  // 2 MB
__device__ float g_o[(size_t)S_ * H_ * D_];      // 32 MB
__device__ float g_or[S_ * G_ * OR_];            // 16 MB

// ==================== generic GEMM: C[M,N] = A[M,K] * B[N,K]^T ====================
__global__ void __launch_bounds__(256) gemm_abt(
    const float* __restrict__ A, int lda,
    const float* __restrict__ B, int ldb,
    float* __restrict__ C, int ldc, int K)
{
    __shared__ float As[16][68];
    __shared__ float Bs[16][68];
    const int tid = threadIdx.x;
    const int tx = tid & 15, ty = tid >> 4;
    const int lr = tid >> 2, lq = tid & 3;
    const float* Ab = A + (size_t)(blockIdx.x * 64 + lr) * lda + lq * 4;
    const float* Bb = B + (size_t)(blockIdx.y * 64 + lr) * ldb + lq * 4;
    float acc[4][4] = {};
    for (int k0 = 0; k0 < K; k0 += 16) {
        float4 av = *(const float4*)(Ab + k0);
        float4 bv = *(const float4*)(Bb + k0);
        As[lq*4+0][lr] = av.x; As[lq*4+1][lr] = av.y;
        As[lq*4+2][lr] = av.z; As[lq*4+3][lr] = av.w;
        Bs[lq*4+0][lr] = bv.x; Bs[lq*4+1][lr] = bv.y;
        Bs[lq*4+2][lr] = bv.z; Bs[lq*4+3][lr] = bv.w;
        __syncthreads();
        #pragma unroll
        for (int k = 0; k < 16; k++) {
            float4 a = *(const float4*)&As[k][ty * 4];
            float4 b = *(const float4*)&Bs[k][tx * 4];
            float ar[4] = {a.x, a.y, a.z, a.w};
            float br[4] = {b.x, b.y, b.z, b.w};
            #pragma unroll
            for (int i = 0; i < 4; i++)
                #pragma unroll
                for (int j = 0; j < 4; j++)
                    acc[i][j] += ar[i] * br[j];
        }
        __syncthreads();
    }
    float* Cp = C + (size_t)(blockIdx.x * 64 + ty * 4) * ldc + blockIdx.y * 64 + tx * 4;
    #pragma unroll
    for (int i = 0; i < 4; i++) {
        float4 v = make_float4(acc[i][0], acc[i][1], acc[i][2], acc[i][3]);
        *(float4*)(Cp + (size_t)i * ldc) = v;
    }
}

// ==================== RMS norm ====================
__global__ void rmsnorm_rows(float* __restrict__ x, const float* __restrict__ w, int L)
{
    int row = blockIdx.x;
    float* p = x + (size_t)row * L;
    float ss = 0.f;
    for (int i = threadIdx.x; i < L; i += blockDim.x) { float v = p[i]; ss += v * v; }
    __shared__ float red[8];
    #pragma unroll
    for (int o = 16; o; o >>= 1) ss += __shfl_xor_sync(0xffffffffu, ss, o);
    if ((threadIdx.x & 31) == 0) red[threadIdx.x >> 5] = ss;
    __syncthreads();
    if (threadIdx.x < 32) {
        float v = (threadIdx.x < 8) ? red[threadIdx.x] : 0.f;
        #pragma unroll
        for (int o = 4; o; o >>= 1) v += __shfl_xor_sync(0xffffffffu, v, o);
        if (threadIdx.x == 0) red[0] = v;
    }
    __syncthreads();
    float inv = rsqrtf(red[0] / (float)L + EPS_);
    for (int i = threadIdx.x; i < L; i += blockDim.x) p[i] = p[i] * inv * w[i];
}

// ==================== q prep: head-norm + RoPE ====================
__global__ void qprep(float* __restrict__ q, const float* __restrict__ freqs)
{
    int s = blockIdx.x, h = blockIdx.y;
    float* p = q + ((size_t)s * H_ + h) * D_;
    int t = threadIdx.x;  // 256
    float v = p[t];
    float ss = v * v;
    __shared__ float red[8];
    __shared__ float rowbuf[D_];
    #pragma unroll
    for (int o = 16; o; o >>= 1) ss += __shfl_xor_sync(0xffffffffu, ss, o);
    if ((t & 31) == 0) red[t >> 5] = ss;
    __syncthreads();
    if (t < 32) {
        float r = (t < 8) ? red[t] : 0.f;
        #pragma unroll
        for (int o = 4; o; o >>= 1) r += __shfl_xor_sync(0xffffffffu, r, o);
        if (t == 0) red[0] = r;
    }
    __syncthreads();
    float inv = rsqrtf(red[0] / (float)D_ + EPS_);
    v *= inv;
    rowbuf[t] = v;
    __syncthreads();
    float outv = v;
    if (t >= NOPE_) {
        int i = (t - NOPE_) >> 1;
        float f = freqs[s * RH_ + i];
        float c = cosf(f), sn = sinf(f);
        float x1 = rowbuf[NOPE_ + 2 * i], x2 = rowbuf[NOPE_ + 2 * i + 1];
        outv = ((t & 1) == 0) ? (x1 * c - x2 * sn) : (x1 * sn + x2 * c);
    }
    p[t] = outv;
}

// ==================== kv prep: rms + RoPE ====================
__global__ void kvprep(float* __restrict__ kv, const float* __restrict__ w,
                       const float* __restrict__ freqs)
{
    int s = blockIdx.x;
    float* p = kv + (size_t)s * D_;
    int t = threadIdx.x;  // 256
    float v = p[t];
    float ss = v * v;
    __shared__ float red[8];
    __shared__ float rowbuf[D_];
    #pragma unroll
    for (int o = 16; o; o >>= 1) ss += __shfl_xor_sync(0xffffffffu, ss, o);
    if ((t & 31) == 0) red[t >> 5] = ss;
    __syncthreads();
    if (t < 32) {
        float r = (t < 8) ? red[t] : 0.f;
        #pragma unroll
        for (int o = 4; o; o >>= 1) r += __shfl_xor_sync(0xffffffffu, r, o);
        if (t == 0) red[0] = r;
    }
    __syncthreads();
    float inv = rsqrtf(red[0] / (float)D_ + EPS_);
    v = v * inv * w[t];
    rowbuf[t] = v;
    __syncthreads();
    float outv = v;
    if (t >= NOPE_) {
        int i = (t - NOPE_) >> 1;
        float f = freqs[s * RH_ + i];
        float c = cosf(f), sn = sinf(f);
        float x1 = rowbuf[NOPE_ + 2 * i], x2 = rowbuf[NOPE_ + 2 * i + 1];
        outv = ((t & 1) == 0) ? (x1 * c - x2 * sn) : (x1 * sn + x2 * c);
    }
    p[t] = outv;
}

// ==================== flash attention, GEMM-style, 64q x 64k tiles ====================
// smem layout (floats):
//   Qs  [256][68]  k-major Q        17408
//   KVk [256][68]  k-major KV tile  17408
//   KVt [ 64][256] t-major KV tile  16384
//   Pt  [ 64][68]  transposed probs  4352
//   rowm/rowl/rowa [64] each          192
#define QS_OFF   0
#define KVK_OFF  (QS_OFF + 256*68)
#define KVT_OFF  (KVK_OFF + 256*68)
#define PT_OFF   (KVT_OFF + 64*256)
#define RM_OFF   (PT_OFF + 64*68)
#define RL_OFF   (RM_OFF + 64)
#define RA_OFF   (RL_OFF + 64)
#define ATTN_SMEM_FLOATS (RA_OFF + 64)

__global__ void __launch_bounds__(256) attn_kernel(
    const float* __restrict__ q, const float* __restrict__ kv,
    const float* __restrict__ sink, float* __restrict__ o)
{
    extern __shared__ float sm[];
    float* Qs  = sm + QS_OFF;
    float* KVk = sm + KVK_OFF;
    float* KVt = sm + KVT_OFF;
    float* Pt  = sm + PT_OFF;
    float* rowm = sm + RM_OFF;
    float* rowl = sm + RL_OFF;
    float* rowa = sm + RA_OFF;

    const int qb = (int)(gridDim.x - 1 - blockIdx.x);   // heavy blocks first
    const int h  = blockIdx.y;
    const int s0 = qb * 64;
    const int tid = threadIdx.x;
    const int tx = tid & 15, ty = tid >> 4;
    const int lr = tid >> 2, lq = tid & 3;   // loader mapping: row, k-quad base

    // ---- load Q tile into Qs (k-major, transposed on store) ----
    #pragma unroll
    for (int j = 0; j < 16; j++) {
        int kq = lq + j * 4;  // 0..63
        float4 v = *(const float4*)&q[((size_t)(s0 + lr) * H_ + h) * D_ + kq * 4];
        Qs[(kq*4+0)*68 + lr] = v.x;
        Qs[(kq*4+1)*68 + lr] = v.y;
        Qs[(kq*4+2)*68 + lr] = v.z;
        Qs[(kq*4+3)*68 + lr] = v.w;
    }
    // init row stats
    if (tid < 64) { rowm[tid] = -1e30f; rowl[tid] = 0.f; }

    // o accumulator: rows ty*4+i, cols tx*4 + 64*g
    float4 oa[4][4];
    #pragma unroll
    for (int i = 0; i < 4; i++)
        #pragma unroll
        for (int g = 0; g < 4; g++) oa[i][g] = make_float4(0.f,0.f,0.f,0.f);

    const int ntiles = qb + 1;
    for (int t0 = 0; t0 < ntiles; t0++) {
        __syncthreads();   // previous o-update done; smem free
        // ---- load KV tile: KVt (row-major) + KVk (k-major) ----
        #pragma unroll
        for (int j = 0; j < 16; j++) {
            int kq = lq + j * 4;
            float4 v = *(const float4*)&kv[(size_t)(t0 * 64 + lr) * D_ + kq * 4];
            *(float4*)&KVt[lr * 256 + kq * 4] = v;
            KVk[(kq*4+0)*68 + lr] = v.x;
            KVk[(kq*4+1)*68 + lr] = v.y;
            KVk[(kq*4+2)*68 + lr] = v.z;
            KVk[(kq*4+3)*68 + lr] = v.w;
        }
        __syncthreads();

        // ---- scores: S[r][t] = sum_k Q[r][k] * KV[t][k] ----
        float acc[4][4] = {};
        #pragma unroll 4
        for (int k = 0; k < 256; k++) {
            float4 a = *(const float4*)&Qs[k*68 + ty*4];
            float4 b = *(const float4*)&KVk[k*68 + tx*4];
            float ar[4] = {a.x, a.y, a.z, a.w};
            float br[4] = {b.x, b.y, b.z, b.w};
            #pragma unroll
            for (int i = 0; i < 4; i++)
                #pragma unroll
                for (int j = 0; j < 4; j++)
                    acc[i][j] += ar[i] * br[j];
        }
        // write transposed+scaled+masked to Pt[t][r]
        #pragma unroll
        for (int j = 0; j < 4; j++) {
            int kt = t0 * 64 + tx * 4 + j;
            #pragma unroll
            for (int i = 0; i < 4; i++) {
                int sr = s0 + ty * 4 + i;
                float v = acc[i][j] * SCALE_;
                if (kt > sr) v = -1e30f;
                Pt[(tx*4+j)*68 + ty*4+i] = v;
            }
        }
        __syncthreads();

        // ---- row-wise online softmax: 4 lanes per row ----
        {
            int r = tid >> 2, sub = tid & 3;
            float vals[16];
            float mloc = -1e30f;
            #pragma unroll
            for (int tt = 0; tt < 16; tt++) {
                vals[tt] = Pt[(sub*16+tt)*68 + r];
                mloc = fmaxf(mloc, vals[tt]);
            }
            mloc = fmaxf(mloc, __shfl_xor_sync(0xffffffffu, mloc, 1));
            mloc = fmaxf(mloc, __shfl_xor_sync(0xffffffffu, mloc, 2));
            float mold = rowm[r];
            float mnew = fmaxf(mold, mloc);
            float s = 0.f;
            #pragma unroll
            for (int tt = 0; tt < 16; tt++) {
                float e = __expf(vals[tt] - mnew);
                Pt[(sub*16+tt)*68 + r] = e;
                s += e;
            }
            s += __shfl_xor_sync(0xffffffffu, s, 1);
            s += __shfl_xor_sync(0xffffffffu, s, 2);
            if (sub == 0) {
                float alpha = __expf(mold - mnew);
                rowa[r] = alpha;
                rowl[r] = rowl[r] * alpha + s;
                rowm[r] = mnew;
            }
        }
        __syncthreads();

        // ---- rescale o, then o += P * KV ----
        float al[4];
        #pragma unroll
        for (int i = 0; i < 4; i++) al[i] = rowa[ty*4+i];
        #pragma unroll
        for (int i = 0; i < 4; i++)
            #pragma unroll
            for (int g = 0; g < 4; g++) {
                oa[i][g].x *= al[i]; oa[i][g].y *= al[i];
                oa[i][g].z *= al[i]; oa[i][g].w *= al[i];
            }
        #pragma unroll 2
        for (int t = 0; t < 64; t++) {
            float4 a = *(const float4*)&Pt[t*68 + ty*4];
            float ar[4] = {a.x, a.y, a.z, a.w};
            #pragma unroll
            for (int g = 0; g < 4; g++) {
                float4 b = *(const float4*)&KVt[t*256 + tx*4 + g*64];
                #pragma unroll
                for (int i = 0; i < 4; i++) {
                    oa[i][g].x += ar[i] * b.x;
                    oa[i][g].y += ar[i] * b.y;
                    oa[i][g].z += ar[i] * b.z;
                    oa[i][g].w += ar[i] * b.w;
                }
            }
        }
    }

    // ---- finalize: divide by (l + exp(sink - m)), write out ----
    float sk = sink[h];
    #pragma unroll
    for (int i = 0; i < 4; i++) {
        int r = ty * 4 + i;
        float denom = rowl[r] + __expf(sk - rowm[r]);
        float inv = 1.f / denom;
        int sr = s0 + r;
        float* op = o + ((size_t)sr * H_ + h) * D_ + tx * 4;
        #pragma unroll
        for (int g = 0; g < 4; g++) {
            float4 v = make_float4(oa[i][g].x*inv, oa[i][g].y*inv,
                                   oa[i][g].z*inv, oa[i][g].w*inv);
            *(float4*)(op + g * 64) = v;
        }
    }
}

// ==================== conjugate RoPE on o's last 64 dims ====================
__global__ void o_rope_conj(float* __restrict__ o, const float* __restrict__ freqs)
{
    int s = blockIdx.x, h = blockIdx.y;
    int i = threadIdx.x;  // 32
    float* p = o + ((size_t)s * H_ + h) * D_ + NOPE_;
    float f = freqs[s * RH_ + i];
    float c = cosf(f), sn = sinf(f);
    float x1 = p[2 * i], x2 = p[2 * i + 1];
    p[2 * i]     = x1 * c + x2 * sn;
    p[2 * i + 1] = x2 * c - x1 * sn;
}

// ==================== launch ====================
extern "C" void kernel_launch(void* const* d_in, const int* in_sizes, int n_in,
                              void* d_out, int out_size)
{
    const float* x         = (const float*)d_in[0];
    const float* freqs     = (const float*)d_in[1];
    const float* wq_a      = (const float*)d_in[2];
    const float* q_norm_w  = (const float*)d_in[3];
    const float* wq_b      = (const float*)d_in[4];
    const float* wkv       = (const float*)d_in[5];
    const float* kv_norm_w = (const float*)d_in[6];
    const float* wo_a_w    = (const float*)d_in[7];
    const float* wo_b      = (const float*)d_in[8];
    const float* attn_sink = (const float*)d_in[9];
    float* out = (float*)d_out;

    float *qa, *qbuf, *kvbuf, *obuf, *orbuf;
    cudaGetSymbolAddress((void**)&qa,    g_qa);
    cudaGetSymbolAddress((void**)&qbuf,  g_q);
    cudaGetSymbolAddress((void**)&kvbuf, g_kv);
    cudaGetSymbolAddress((void**)&obuf,  g_o);
    cudaGetSymbolAddress((void**)&orbuf, g_or);

    static int smem_set = 0;
    if (!smem_set) {
        cudaFuncSetAttribute(attn_kernel, cudaFuncAttributeMaxDynamicSharedMemorySize,
                             ATTN_SMEM_FLOATS * (int)sizeof(float));
        smem_set = 1;
    }

    dim3 blk(256);
    // q_a = x @ wq_a^T    [2048,1024]
    gemm_abt<<<dim3(32, 16), blk>>>(x, HID_, wq_a, HID_, qa, QL_, HID_);
    // kv_raw = x @ wkv^T  [2048,256]
    gemm_abt<<<dim3(32, 4), blk>>>(x, HID_, wkv, HID_, kvbuf, D_, HID_);
    // rms(q_a)
    rmsnorm_rows<<<S_, 256>>>(qa, q_norm_w, QL_);
    // q = q_a @ wq_b^T    [2048,4096]
    gemm_abt<<<dim3(32, 64), blk>>>(qa, QL_, wq_b, QL_, qbuf, H_ * D_, QL_);
    // kv: rms + rope
    kvprep<<<S_, 256>>>(kvbuf, kv_norm_w, freqs);
    // q: head-norm + rope
    qprep<<<dim3(S_, H_), 256>>>(qbuf, freqs);
    // attention (64-row q tiles)
    attn_kernel<<<dim3(S_ / 64, H_), blk, ATTN_SMEM_FLOATS * (int)sizeof(float)>>>(
        qbuf, kvbuf, attn_sink, obuf);
    // conj rope on o
    o_rope_conj<<<dim3(S_, H_), 32>>>(obuf, freqs);
    // grouped low-rank
    for (int g = 0; g < G_; g++)
        gemm_abt<<<dim3(32, 8), blk>>>(obuf + g * 1024, H_ * D_,
                                       wo_a_w + (size_t)g * OR_ * 1024, 1024,
                                       orbuf + g * OR_, G_ * OR_, 1024);
    // out = o_r @ wo_b^T  [2048,2048]
    gemm_abt<<<dim3(32, 32), blk>>>(orbuf, G_ * OR_, wo_b, HID_, out, HID_, G_ * OR_);
}

// round 3
// speedup vs baseline: 5.1413x; 1.1006x over previous
#include <cuda_runtime.h>
#include <math.h>

#define S_    2048
#define HID_  2048
#define H_    16
#define D_    256
#define NOPE_ 192
#define RH_   32      // R/2
#define QL_   1024
#define OR_   512
#define G_    4
#define EPS_  1e-6f
#define SCALE_ 0.0625f   // 256^-0.5

// -------- scratch (no allocations allowed) --------
__device__ float g_qa[S_ * QL_];                 // 8 MB
__device__ float g_q[(size_t)S_ * H_ * D_];      // 32 MB
__device__ float g_kv[S_ * D_];                  // 2 MB
__device__ float g_o[(size_t)S_ * H_ * D_];      // 32 MB
__device__ float g_or[S_ * G_ * OR_];            // 16 MB

// ==================== big GEMM: C[M,N] = A[M,K] * B[N,K]^T ====================
// 128x128 tile, BK=8, double-buffered, 256 threads, 8x8 micro-tile (2x2 quads).
// Requires M%128==0, N%128==0, K%8==0.
__global__ void __launch_bounds__(256) gemm128(
    const float* __restrict__ A, int lda,
    const float* __restrict__ B, int ldb,
    float* __restrict__ C, int ldc, int K)
{
    __shared__ float As[2][8][132];
    __shared__ float Bs[2][8][132];
    const int tid = threadIdx.x;
    const int tx = tid & 15, ty = tid >> 4;
    const int lrow = tid >> 1, lk = (tid & 1) * 4;

    const float* Ap = A + (size_t)(blockIdx.x * 128 + lrow) * lda + lk;
    const float* Bp = B + (size_t)(blockIdx.y * 128 + lrow) * ldb + lk;

    // preload k-block 0
    {
        float4 av = *(const float4*)Ap;
        float4 bv = *(const float4*)Bp;
        As[0][lk+0][lrow] = av.x; As[0][lk+1][lrow] = av.y;
        As[0][lk+2][lrow] = av.z; As[0][lk+3][lrow] = av.w;
        Bs[0][lk+0][lrow] = bv.x; Bs[0][lk+1][lrow] = bv.y;
        Bs[0][lk+2][lrow] = bv.z; Bs[0][lk+3][lrow] = bv.w;
    }
    __syncthreads();

    float acc[8][8] = {};
    const int nkb = K >> 3;
    for (int kb = 0; kb < nkb; kb++) {
        const int cur = kb & 1, nxt = cur ^ 1;
        float4 av, bv;
        const bool more = (kb + 1) < nkb;
        if (more) {
            av = *(const float4*)(Ap + (size_t)(kb + 1) * 8);
            bv = *(const float4*)(Bp + (size_t)(kb + 1) * 8);
        }
        #pragma unroll
        for (int k = 0; k < 8; k++) {
            float4 a0 = *(const float4*)&As[cur][k][ty * 4];
            float4 a1 = *(const float4*)&As[cur][k][64 + ty * 4];
            float4 b0 = *(const float4*)&Bs[cur][k][tx * 4];
            float4 b1 = *(const float4*)&Bs[cur][k][64 + tx * 4];
            float ar[8] = {a0.x,a0.y,a0.z,a0.w, a1.x,a1.y,a1.z,a1.w};
            float br[8] = {b0.x,b0.y,b0.z,b0.w, b1.x,b1.y,b1.z,b1.w};
            #pragma unroll
            for (int i = 0; i < 8; i++)
                #pragma unroll
                for (int j = 0; j < 8; j++)
                    acc[i][j] += ar[i] * br[j];
        }
        if (more) {
            As[nxt][lk+0][lrow] = av.x; As[nxt][lk+1][lrow] = av.y;
            As[nxt][lk+2][lrow] = av.z; As[nxt][lk+3][lrow] = av.w;
            Bs[nxt][lk+0][lrow] = bv.x; Bs[nxt][lk+1][lrow] = bv.y;
            Bs[nxt][lk+2][lrow] = bv.z; Bs[nxt][lk+3][lrow] = bv.w;
            __syncthreads();
        }
    }

    const int bx = blockIdx.x * 128, by = blockIdx.y * 128;
    #pragma unroll
    for (int ih = 0; ih < 2; ih++) {
        #pragma unroll
        for (int i = 0; i < 4; i++) {
            int r = bx + ih * 64 + ty * 4 + i;
            float* Cp = C + (size_t)r * ldc + by;
            int ai = ih * 4 + i;
            *(float4*)(Cp + tx * 4) =
                make_float4(acc[ai][0], acc[ai][1], acc[ai][2], acc[ai][3]);
            *(float4*)(Cp + 64 + tx * 4) =
                make_float4(acc[ai][4], acc[ai][5], acc[ai][6], acc[ai][7]);
        }
    }
}

// ==================== small GEMM: C[M,N] = A[M,K] * B[N,K]^T (64x64) ====================
__global__ void __launch_bounds__(256) gemm_abt(
    const float* __restrict__ A, int lda,
    const float* __restrict__ B, int ldb,
    float* __restrict__ C, int ldc, int K)
{
    __shared__ float As[16][68];
    __shared__ float Bs[16][68];
    const int tid = threadIdx.x;
    const int tx = tid & 15, ty = tid >> 4;
    const int lr = tid >> 2, lq = tid & 3;
    const float* Ab = A + (size_t)(blockIdx.x * 64 + lr) * lda + lq * 4;
    const float* Bb = B + (size_t)(blockIdx.y * 64 + lr) * ldb + lq * 4;
    float acc[4][4] = {};
    for (int k0 = 0; k0 < K; k0 += 16) {
        float4 av = *(const float4*)(Ab + k0);
        float4 bv = *(const float4*)(Bb + k0);
        As[lq*4+0][lr] = av.x; As[lq*4+1][lr] = av.y;
        As[lq*4+2][lr] = av.z; As[lq*4+3][lr] = av.w;
        Bs[lq*4+0][lr] = bv.x; Bs[lq*4+1][lr] = bv.y;
        Bs[lq*4+2][lr] = bv.z; Bs[lq*4+3][lr] = bv.w;
        __syncthreads();
        #pragma unroll
        for (int k = 0; k < 16; k++) {
            float4 a = *(const float4*)&As[k][ty * 4];
            float4 b = *(const float4*)&Bs[k][tx * 4];
            float ar[4] = {a.x, a.y, a.z, a.w};
            float br[4] = {b.x, b.y, b.z, b.w};
            #pragma unroll
            for (int i = 0; i < 4; i++)
                #pragma unroll
                for (int j = 0; j < 4; j++)
                    acc[i][j] += ar[i] * br[j];
        }
        __syncthreads();
    }
    float* Cp = C + (size_t)(blockIdx.x * 64 + ty * 4) * ldc + blockIdx.y * 64 + tx * 4;
    #pragma unroll
    for (int i = 0; i < 4; i++) {
        float4 v = make_float4(acc[i][0], acc[i][1], acc[i][2], acc[i][3]);
        *(float4*)(Cp + (size_t)i * ldc) = v;
    }
}

// ==================== RMS norm ====================
__global__ void rmsnorm_rows(float* __restrict__ x, const float* __restrict__ w, int L)
{
    int row = blockIdx.x;
    float* p = x + (size_t)row * L;
    float ss = 0.f;
    for (int i = threadIdx.x; i < L; i += blockDim.x) { float v = p[i]; ss += v * v; }
    __shared__ float red[8];
    #pragma unroll
    for (int o = 16; o; o >>= 1) ss += __shfl_xor_sync(0xffffffffu, ss, o);
    if ((threadIdx.x & 31) == 0) red[threadIdx.x >> 5] = ss;
    __syncthreads();
    if (threadIdx.x < 32) {
        float v = (threadIdx.x < 8) ? red[threadIdx.x] : 0.f;
        #pragma unroll
        for (int o = 4; o; o >>= 1) v += __shfl_xor_sync(0xffffffffu, v, o);
        if (threadIdx.x == 0) red[0] = v;
    }
    __syncthreads();
    float inv = rsqrtf(red[0] / (float)L + EPS_);
    for (int i = threadIdx.x; i < L; i += blockDim.x) p[i] = p[i] * inv * w[i];
}

// ==================== q prep: head-norm + RoPE ====================
__global__ void qprep(float* __restrict__ q, const float* __restrict__ freqs)
{
    int s = blockIdx.x, h = blockIdx.y;
    float* p = q + ((size_t)s * H_ + h) * D_;
    int t = threadIdx.x;  // 256
    float v = p[t];
    float ss = v * v;
    __shared__ float red[8];
    __shared__ float rowbuf[D_];
    #pragma unroll
    for (int o = 16; o; o >>= 1) ss += __shfl_xor_sync(0xffffffffu, ss, o);
    if ((t & 31) == 0) red[t >> 5] = ss;
    __syncthreads();
    if (t < 32) {
        float r = (t < 8) ? red[t] : 0.f;
        #pragma unroll
        for (int o = 4; o; o >>= 1) r += __shfl_xor_sync(0xffffffffu, r, o);
        if (t == 0) red[0] = r;
    }
    __syncthreads();
    float inv = rsqrtf(red[0] / (float)D_ + EPS_);
    v *= inv;
    rowbuf[t] = v;
    __syncthreads();
    float outv = v;
    if (t >= NOPE_) {
        int i = (t - NOPE_) >> 1;
        float f = freqs[s * RH_ + i];
        float c = cosf(f), sn = sinf(f);
        float x1 = rowbuf[NOPE_ + 2 * i], x2 = rowbuf[NOPE_ + 2 * i + 1];
        outv = ((t & 1) == 0) ? (x1 * c - x2 * sn) : (x1 * sn + x2 * c);
    }
    p[t] = outv;
}

// ==================== kv prep: rms + RoPE ====================
__global__ void kvprep(float* __restrict__ kv, const float* __restrict__ w,
                       const float* __restrict__ freqs)
{
    int s = blockIdx.x;
    float* p = kv + (size_t)s * D_;
    int t = threadIdx.x;  // 256
    float v = p[t];
    float ss = v * v;
    __shared__ float red[8];
    __shared__ float rowbuf[D_];
    #pragma unroll
    for (int o = 16; o; o >>= 1) ss += __shfl_xor_sync(0xffffffffu, ss, o);
    if ((t & 31) == 0) red[t >> 5] = ss;
    __syncthreads();
    if (t < 32) {
        float r = (t < 8) ? red[t] : 0.f;
        #pragma unroll
        for (int o = 4; o; o >>= 1) r += __shfl_xor_sync(0xffffffffu, r, o);
        if (t == 0) red[0] = r;
    }
    __syncthreads();
    float inv = rsqrtf(red[0] / (float)D_ + EPS_);
    v = v * inv * w[t];
    rowbuf[t] = v;
    __syncthreads();
    float outv = v;
    if (t >= NOPE_) {
        int i = (t - NOPE_) >> 1;
        float f = freqs[s * RH_ + i];
        float c = cosf(f), sn = sinf(f);
        float x1 = rowbuf[NOPE_ + 2 * i], x2 = rowbuf[NOPE_ + 2 * i + 1];
        outv = ((t & 1) == 0) ? (x1 * c - x2 * sn) : (x1 * sn + x2 * c);
    }
    p[t] = outv;
}

// ==================== flash attention, GEMM-style, 64q x 64k tiles ====================
#define QS_OFF   0
#define KVK_OFF  (QS_OFF + 256*68)
#define KVT_OFF  (KVK_OFF + 256*68)
#define PT_OFF   (KVT_OFF + 64*256)
#define RM_OFF   (PT_OFF + 64*68)
#define RL_OFF   (RM_OFF + 64)
#define RA_OFF   (RL_OFF + 64)
#define ATTN_SMEM_FLOATS (RA_OFF + 64)

__global__ void __launch_bounds__(256) attn_kernel(
    const float* __restrict__ q, const float* __restrict__ kv,
    const float* __restrict__ sink, float* __restrict__ o)
{
    extern __shared__ float sm[];
    float* Qs  = sm + QS_OFF;
    float* KVk = sm + KVK_OFF;
    float* KVt = sm + KVT_OFF;
    float* Pt  = sm + PT_OFF;
    float* rowm = sm + RM_OFF;
    float* rowl = sm + RL_OFF;
    float* rowa = sm + RA_OFF;

    const int qb = (int)(gridDim.x - 1 - blockIdx.x);   // heavy blocks first
    const int h  = blockIdx.y;
    const int s0 = qb * 64;
    const int tid = threadIdx.x;
    const int tx = tid & 15, ty = tid >> 4;
    const int lr = tid >> 2, lq = tid & 3;

    #pragma unroll
    for (int j = 0; j < 16; j++) {
        int kq = lq + j * 4;
        float4 v = *(const float4*)&q[((size_t)(s0 + lr) * H_ + h) * D_ + kq * 4];
        Qs[(kq*4+0)*68 + lr] = v.x;
        Qs[(kq*4+1)*68 + lr] = v.y;
        Qs[(kq*4+2)*68 + lr] = v.z;
        Qs[(kq*4+3)*68 + lr] = v.w;
    }
    if (tid < 64) { rowm[tid] = -1e30f; rowl[tid] = 0.f; }

    float4 oa[4][4];
    #pragma unroll
    for (int i = 0; i < 4; i++)
        #pragma unroll
        for (int g = 0; g < 4; g++) oa[i][g] = make_float4(0.f,0.f,0.f,0.f);

    const int ntiles = qb + 1;
    for (int t0 = 0; t0 < ntiles; t0++) {
        __syncthreads();
        #pragma unroll
        for (int j = 0; j < 16; j++) {
            int kq = lq + j * 4;
            float4 v = *(const float4*)&kv[(size_t)(t0 * 64 + lr) * D_ + kq * 4];
            *(float4*)&KVt[lr * 256 + kq * 4] = v;
            KVk[(kq*4+0)*68 + lr] = v.x;
            KVk[(kq*4+1)*68 + lr] = v.y;
            KVk[(kq*4+2)*68 + lr] = v.z;
            KVk[(kq*4+3)*68 + lr] = v.w;
        }
        __syncthreads();

        float acc[4][4] = {};
        #pragma unroll 4
        for (int k = 0; k < 256; k++) {
            float4 a = *(const float4*)&Qs[k*68 + ty*4];
            float4 b = *(const float4*)&KVk[k*68 + tx*4];
            float ar[4] = {a.x, a.y, a.z, a.w};
            float br[4] = {b.x, b.y, b.z, b.w};
            #pragma unroll
            for (int i = 0; i < 4; i++)
                #pragma unroll
                for (int j = 0; j < 4; j++)
                    acc[i][j] += ar[i] * br[j];
        }
        #pragma unroll
        for (int j = 0; j < 4; j++) {
            int kt = t0 * 64 + tx * 4 + j;
            #pragma unroll
            for (int i = 0; i < 4; i++) {
                int sr = s0 + ty * 4 + i;
                float v = acc[i][j] * SCALE_;
                if (kt > sr) v = -1e30f;
                Pt[(tx*4+j)*68 + ty*4+i] = v;
            }
        }
        __syncthreads();

        {
            int r = tid >> 2, sub = tid & 3;
            float vals[16];
            float mloc = -1e30f;
            #pragma unroll
            for (int tt = 0; tt < 16; tt++) {
                vals[tt] = Pt[(sub*16+tt)*68 + r];
                mloc = fmaxf(mloc, vals[tt]);
            }
            mloc = fmaxf(mloc, __shfl_xor_sync(0xffffffffu, mloc, 1));
            mloc = fmaxf(mloc, __shfl_xor_sync(0xffffffffu, mloc, 2));
            float mold = rowm[r];
            float mnew = fmaxf(mold, mloc);
            float s = 0.f;
            #pragma unroll
            for (int tt = 0; tt < 16; tt++) {
                float e = __expf(vals[tt] - mnew);
                Pt[(sub*16+tt)*68 + r] = e;
                s += e;
            }
            s += __shfl_xor_sync(0xffffffffu, s, 1);
            s += __shfl_xor_sync(0xffffffffu, s, 2);
            if (sub == 0) {
                float alpha = __expf(mold - mnew);
                rowa[r] = alpha;
                rowl[r] = rowl[r] * alpha + s;
                rowm[r] = mnew;
            }
        }
        __syncthreads();

        float al[4];
        #pragma unroll
        for (int i = 0; i < 4; i++) al[i] = rowa[ty*4+i];
        #pragma unroll
        for (int i = 0; i < 4; i++)
            #pragma unroll
            for (int g = 0; g < 4; g++) {
                oa[i][g].x *= al[i]; oa[i][g].y *= al[i];
                oa[i][g].z *= al[i]; oa[i][g].w *= al[i];
            }
        #pragma unroll 2
        for (int t = 0; t < 64; t++) {
            float4 a = *(const float4*)&Pt[t*68 + ty*4];
            float ar[4] = {a.x, a.y, a.z, a.w};
            #pragma unroll
            for (int g = 0; g < 4; g++) {
                float4 b = *(const float4*)&KVt[t*256 + tx*4 + g*64];
                #pragma unroll
                for (int i = 0; i < 4; i++) {
                    oa[i][g].x += ar[i] * b.x;
                    oa[i][g].y += ar[i] * b.y;
                    oa[i][g].z += ar[i] * b.z;
                    oa[i][g].w += ar[i] * b.w;
                }
            }
        }
    }

    float sk = sink[h];
    #pragma unroll
    for (int i = 0; i < 4; i++) {
        int r = ty * 4 + i;
        float denom = rowl[r] + __expf(sk - rowm[r]);
        float inv = 1.f / denom;
        int sr = s0 + r;
        float* op = o + ((size_t)sr * H_ + h) * D_ + tx * 4;
        #pragma unroll
        for (int g = 0; g < 4; g++) {
            float4 v = make_float4(oa[i][g].x*inv, oa[i][g].y*inv,
                                   oa[i][g].z*inv, oa[i][g].w*inv);
            *(float4*)(op + g * 64) = v;
        }
    }
}

// ==================== conjugate RoPE on o's last 64 dims ====================
__global__ void o_rope_conj(float* __restrict__ o, const float* __restrict__ freqs)
{
    int s = blockIdx.x, h = blockIdx.y;
    int i = threadIdx.x;  // 32
    float* p = o + ((size_t)s * H_ + h) * D_ + NOPE_;
    float f = freqs[s * RH_ + i];
    float c = cosf(f), sn = sinf(f);
    float x1 = p[2 * i], x2 = p[2 * i + 1];
    p[2 * i]     = x1 * c + x2 * sn;
    p[2 * i + 1] = x2 * c - x1 * sn;
}

// ==================== launch ====================
extern "C" void kernel_launch(void* const* d_in, const int* in_sizes, int n_in,
                              void* d_out, int out_size)
{
    const float* x         = (const float*)d_in[0];
    const float* freqs     = (const float*)d_in[1];
    const float* wq_a      = (const float*)d_in[2];
    const float* q_norm_w  = (const float*)d_in[3];
    const float* wq_b      = (const float*)d_in[4];
    const float* wkv       = (const float*)d_in[5];
    const float* kv_norm_w = (const float*)d_in[6];
    const float* wo_a_w    = (const float*)d_in[7];
    const float* wo_b      = (const float*)d_in[8];
    const float* attn_sink = (const float*)d_in[9];
    float* out = (float*)d_out;

    float *qa, *qbuf, *kvbuf, *obuf, *orbuf;
    cudaGetSymbolAddress((void**)&qa,    g_qa);
    cudaGetSymbolAddress((void**)&qbuf,  g_q);
    cudaGetSymbolAddress((void**)&kvbuf, g_kv);
    cudaGetSymbolAddress((void**)&obuf,  g_o);
    cudaGetSymbolAddress((void**)&orbuf, g_or);

    static int smem_set = 0;
    if (!smem_set) {
        cudaFuncSetAttribute(attn_kernel, cudaFuncAttributeMaxDynamicSharedMemorySize,
                             ATTN_SMEM_FLOATS * (int)sizeof(float));
        smem_set = 1;
    }

    dim3 blk(256);
    // q_a = x @ wq_a^T    [2048,1024]  (big)
    gemm128<<<dim3(16, 8), blk>>>(x, HID_, wq_a, HID_, qa, QL_, HID_);
    // kv_raw = x @ wkv^T  [2048,256]  (small-N -> 64x64 kernel, more CTAs)
    gemm_abt<<<dim3(32, 4), blk>>>(x, HID_, wkv, HID_, kvbuf, D_, HID_);
    // rms(q_a)
    rmsnorm_rows<<<S_, 256>>>(qa, q_norm_w, QL_);
    // q = q_a @ wq_b^T    [2048,4096]  (big)
    gemm128<<<dim3(16, 32), blk>>>(qa, QL_, wq_b, QL_, qbuf, H_ * D_, QL_);
    // kv: rms + rope
    kvprep<<<S_, 256>>>(kvbuf, kv_norm_w, freqs);
    // q: head-norm + rope
    qprep<<<dim3(S_, H_), 256>>>(qbuf, freqs);
    // attention (64-row q tiles)
    attn_kernel<<<dim3(S_ / 64, H_), blk, ATTN_SMEM_FLOATS * (int)sizeof(float)>>>(
        qbuf, kvbuf, attn_sink, obuf);
    // conj rope on o
    o_rope_conj<<<dim3(S_, H_), 32>>>(obuf, freqs);
    // grouped low-rank (N=512 -> 64x64 kernel for CTA count)
    for (int g = 0; g < G_; g++)
        gemm_abt<<<dim3(32, 8), blk>>>(obuf + g * 1024, H_ * D_,
                                       wo_a_w + (size_t)g * OR_ * 1024, 1024,
                                       orbuf + g * OR_, G_ * OR_, 1024);
    // out = o_r @ wo_b^T  [2048,2048]  (big)
    gemm128<<<dim3(16, 16), blk>>>(orbuf, G_ * OR_, wo_b, HID_, out, HID_, G_ * OR_);
}

// round 9
// speedup vs baseline: 5.3991x; 1.0501x over previous
#include <cuda_runtime.h>
#include <cuda_bf16.h>
#include <mma.h>
#include <math.h>
#include <stdint.h>

using namespace nvcuda;

#define S_    2048
#define HID_  2048
#define H_    16
#define D_    256
#define NOPE_ 192
#define RH_   32
#define QL_   1024
#define OR_   512
#define G_    4
#define EPS_  1e-6f
#define SCALE_ 0.0625f

// -------- scratch --------
__device__ float g_qa[S_ * QL_];
__device__ float g_q[(size_t)S_ * H_ * D_];
__device__ float g_kv[S_ * D_];
__device__ float g_o[(size_t)S_ * H_ * D_];
__device__ float g_or[S_ * G_ * OR_];

__device__ __forceinline__ uint32_t b2u(__nv_bfloat162 h) {
    return *reinterpret_cast<uint32_t*>(&h);
}

// ==================== WMMA bf16 split GEMM: C[M,N] = A[M,K] * B[N,K]^T ====================
// 128x128 CTA tile, K in 64-chunks -> K'=192 bf16 via [hi|lo|hi] x [hi|hi|lo].
#define WS 208   // smem k-stride (bf16 elems), mult of 16
#define GW_SMEM (2 * 128 * WS * 2 + 256)

__global__ void __launch_bounds__(256) gemm_wmma(
    const float* __restrict__ A, int lda,
    const float* __restrict__ B, int ldb,
    float* __restrict__ C, int ldc, int K,
    long sAz, long sBz, long sCz)
{
    extern __shared__ char smraw[];
    // align to 256B
    __nv_bfloat16* As = (__nv_bfloat16*)(((uintptr_t)smraw + 255) & ~(uintptr_t)255);
    __nv_bfloat16* Bs = As + 128 * WS;

    A += (size_t)blockIdx.z * sAz;
    B += (size_t)blockIdx.z * sBz;
    C += (size_t)blockIdx.z * sCz;

    const int tid = threadIdx.x;
    const int warp = tid >> 5;
    const int wm = warp & 1, wn = warp >> 1;   // 2 x 4 warp grid

    wmma::fragment<wmma::accumulator, 16, 16, 16, float> acc[4][2];
    #pragma unroll
    for (int i = 0; i < 4; i++)
        #pragma unroll
        for (int j = 0; j < 2; j++)
            wmma::fill_fragment(acc[i][j], 0.0f);

    const int r  = tid >> 1;
    const int c0 = (tid & 1) * 32;
    const float* Ap = A + (size_t)(blockIdx.x * 128 + r) * lda + c0;
    const float* Bp = B + (size_t)(blockIdx.y * 128 + r) * ldb + c0;

    const int nkc = K >> 6;
    for (int kc = 0; kc < nkc; kc++) {
        __syncthreads();
        #pragma unroll
        for (int g = 0; g < 8; g++) {
            int k = c0 + g * 4;
            {   // A: [hi | lo | hi]
                float4 v = *(const float4*)(Ap + kc * 64 + g * 4);
                __nv_bfloat162 h01 = __floats2bfloat162_rn(v.x, v.y);
                __nv_bfloat162 h23 = __floats2bfloat162_rn(v.z, v.w);
                __nv_bfloat162 l01 = __floats2bfloat162_rn(
                    v.x - __bfloat162float(__low2bfloat16(h01)),
                    v.y - __bfloat162float(__high2bfloat16(h01)));
                __nv_bfloat162 l23 = __floats2bfloat162_rn(
                    v.z - __bfloat162float(__low2bfloat16(h23)),
                    v.w - __bfloat162float(__high2bfloat16(h23)));
                __nv_bfloat16* row = As + r * WS;
                *(uint32_t*)(row + k)           = b2u(h01);
                *(uint32_t*)(row + k + 2)       = b2u(h23);
                *(uint32_t*)(row + 64 + k)      = b2u(l01);
                *(uint32_t*)(row + 64 + k + 2)  = b2u(l23);
                *(uint32_t*)(row + 128 + k)     = b2u(h01);
                *(uint32_t*)(row + 128 + k + 2) = b2u(h23);
            }
            {   // B: [hi | hi | lo]
                float4 v = *(const float4*)(Bp + kc * 64 + g * 4);
                __nv_bfloat162 h01 = __floats2bfloat162_rn(v.x, v.y);
                __nv_bfloat162 h23 = __floats2bfloat162_rn(v.z, v.w);
                __nv_bfloat162 l01 = __floats2bfloat162_rn(
                    v.x - __bfloat162float(__low2bfloat16(h01)),
                    v.y - __bfloat162float(__high2bfloat16(h01)));
                __nv_bfloat162 l23 = __floats2bfloat162_rn(
                    v.z - __bfloat162float(__low2bfloat16(h23)),
                    v.w - __bfloat162float(__high2bfloat16(h23)));
                __nv_bfloat16* row = Bs + r * WS;
                *(uint32_t*)(row + k)           = b2u(h01);
                *(uint32_t*)(row + k + 2)       = b2u(h23);
                *(uint32_t*)(row + 64 + k)      = b2u(h01);
                *(uint32_t*)(row + 64 + k + 2)  = b2u(h23);
                *(uint32_t*)(row + 128 + k)     = b2u(l01);
                *(uint32_t*)(row + 128 + k + 2) = b2u(l23);
            }
        }
        __syncthreads();

        #pragma unroll 4
        for (int ks = 0; ks < 12; ks++) {
            wmma::fragment<wmma::matrix_a, 16, 16, 16, __nv_bfloat16, wmma::row_major> af[4];
            wmma::fragment<wmma::matrix_b, 16, 16, 16, __nv_bfloat16, wmma::col_major> bf[2];
            #pragma unroll
            for (int i = 0; i < 4; i++)
                wmma::load_matrix_sync(af[i], As + (wm * 64 + i * 16) * WS + ks * 16, WS);
            #pragma unroll
            for (int j = 0; j < 2; j++)
                wmma::load_matrix_sync(bf[j], Bs + (wn * 32 + j * 16) * WS + ks * 16, WS);
            #pragma unroll
            for (int i = 0; i < 4; i++)
                #pragma unroll
                for (int j = 0; j < 2; j++)
                    wmma::mma_sync(acc[i][j], af[i], bf[j], acc[i][j]);
        }
    }

    #pragma unroll
    for (int i = 0; i < 4; i++)
        #pragma unroll
        for (int j = 0; j < 2; j++) {
            float* Cp = C + (size_t)(blockIdx.x * 128 + wm * 64 + i * 16) * ldc
                          + blockIdx.y * 128 + wn * 32 + j * 16;
            wmma::store_matrix_sync(Cp, acc[i][j], ldc, wmma::mem_row_major);
        }
}

// ==================== small fp32 GEMM (64x64) for kv ====================
__global__ void __launch_bounds__(256) gemm_abt(
    const float* __restrict__ A, int lda,
    const float* __restrict__ B, int ldb,
    float* __restrict__ C, int ldc, int K)
{
    __shared__ float As[16][68];
    __shared__ float Bs[16][68];
    const int tid = threadIdx.x;
    const int tx = tid & 15, ty = tid >> 4;
    const int lr = tid >> 2, lq = tid & 3;
    const float* Ab = A + (size_t)(blockIdx.x * 64 + lr) * lda + lq * 4;
    const float* Bb = B + (size_t)(blockIdx.y * 64 + lr) * ldb + lq * 4;
    float acc[4][4] = {};
    for (int k0 = 0; k0 < K; k0 += 16) {
        float4 av = *(const float4*)(Ab + k0);
        float4 bv = *(const float4*)(Bb + k0);
        As[lq*4+0][lr] = av.x; As[lq*4+1][lr] = av.y;
        As[lq*4+2][lr] = av.z; As[lq*4+3][lr] = av.w;
        Bs[lq*4+0][lr] = bv.x; Bs[lq*4+1][lr] = bv.y;
        Bs[lq*4+2][lr] = bv.z; Bs[lq*4+3][lr] = bv.w;
        __syncthreads();
        #pragma unroll
        for (int k = 0; k < 16; k++) {
            float4 a = *(const float4*)&As[k][ty * 4];
            float4 b = *(const float4*)&Bs[k][tx * 4];
            float ar[4] = {a.x, a.y, a.z, a.w};
            float br[4] = {b.x, b.y, b.z, b.w};
            #pragma unroll
            for (int i = 0; i < 4; i++)
                #pragma unroll
                for (int j = 0; j < 4; j++)
                    acc[i][j] += ar[i] * br[j];
        }
        __syncthreads();
    }
    float* Cp = C + (size_t)(blockIdx.x * 64 + ty * 4) * ldc + blockIdx.y * 64 + tx * 4;
    #pragma unroll
    for (int i = 0; i < 4; i++) {
        float4 v = make_float4(acc[i][0], acc[i][1], acc[i][2], acc[i][3]);
        *(float4*)(Cp + (size_t)i * ldc) = v;
    }
}

// ==================== RMS norm ====================
__global__ void rmsnorm_rows(float* __restrict__ x, const float* __restrict__ w, int L)
{
    int row = blockIdx.x;
    float* p = x + (size_t)row * L;
    float ss = 0.f;
    for (int i = threadIdx.x; i < L; i += blockDim.x) { float v = p[i]; ss += v * v; }
    __shared__ float red[8];
    #pragma unroll
    for (int o = 16; o; o >>= 1) ss += __shfl_xor_sync(0xffffffffu, ss, o);
    if ((threadIdx.x & 31) == 0) red[threadIdx.x >> 5] = ss;
    __syncthreads();
    if (threadIdx.x < 32) {
        float v = (threadIdx.x < 8) ? red[threadIdx.x] : 0.f;
        #pragma unroll
        for (int o = 4; o; o >>= 1) v += __shfl_xor_sync(0xffffffffu, v, o);
        if (threadIdx.x == 0) red[0] = v;
    }
    __syncthreads();
    float inv = rsqrtf(red[0] / (float)L + EPS_);
    for (int i = threadIdx.x; i < L; i += blockDim.x) p[i] = p[i] * inv * w[i];
}

// ==================== q prep ====================
__global__ void qprep(float* __restrict__ q, const float* __restrict__ freqs)
{
    int s = blockIdx.x, h = blockIdx.y;
    float* p = q + ((size_t)s * H_ + h) * D_;
    int t = threadIdx.x;
    float v = p[t];
    float ss = v * v;
    __shared__ float red[8];
    __shared__ float rowbuf[D_];
    #pragma unroll
    for (int o = 16; o; o >>= 1) ss += __shfl_xor_sync(0xffffffffu, ss, o);
    if ((t & 31) == 0) red[t >> 5] = ss;
    __syncthreads();
    if (t < 32) {
        float r = (t < 8) ? red[t] : 0.f;
        #pragma unroll
        for (int o = 4; o; o >>= 1) r += __shfl_xor_sync(0xffffffffu, r, o);
        if (t == 0) red[0] = r;
    }
    __syncthreads();
    float inv = rsqrtf(red[0] / (float)D_ + EPS_);
    v *= inv;
    rowbuf[t] = v;
    __syncthreads();
    float outv = v;
    if (t >= NOPE_) {
        int i = (t - NOPE_) >> 1;
        float f = freqs[s * RH_ + i];
        float c = cosf(f), sn = sinf(f);
        float x1 = rowbuf[NOPE_ + 2 * i], x2 = rowbuf[NOPE_ + 2 * i + 1];
        outv = ((t & 1) == 0) ? (x1 * c - x2 * sn) : (x1 * sn + x2 * c);
    }
    p[t] = outv;
}

// ==================== kv prep ====================
__global__ void kvprep(float* __restrict__ kv, const float* __restrict__ w,
                       const float* __restrict__ freqs)
{
    int s = blockIdx.x;
    float* p = kv + (size_t)s * D_;
    int t = threadIdx.x;
    float v = p[t];
    float ss = v * v;
    __shared__ float red[8];
    __shared__ float rowbuf[D_];
    #pragma unroll
    for (int o = 16; o; o >>= 1) ss += __shfl_xor_sync(0xffffffffu, ss, o);
    if ((t & 31) == 0) red[t >> 5] = ss;
    __syncthreads();
    if (t < 32) {
        float r = (t < 8) ? red[t] : 0.f;
        #pragma unroll
        for (int o = 4; o; o >>= 1) r += __shfl_xor_sync(0xffffffffu, r, o);
        if (t == 0) red[0] = r;
    }
    __syncthreads();
    float inv = rsqrtf(red[0] / (float)D_ + EPS_);
    v = v * inv * w[t];
    rowbuf[t] = v;
    __syncthreads();
    float outv = v;
    if (t >= NOPE_) {
        int i = (t - NOPE_) >> 1;
        float f = freqs[s * RH_ + i];
        float c = cosf(f), sn = sinf(f);
        float x1 = rowbuf[NOPE_ + 2 * i], x2 = rowbuf[NOPE_ + 2 * i + 1];
        outv = ((t & 1) == 0) ? (x1 * c - x2 * sn) : (x1 * sn + x2 * c);
    }
    p[t] = outv;
}

// ==================== flash attention (fp32, unchanged) ====================
#define QS_OFF   0
#define KVK_OFF  (QS_OFF + 256*68)
#define KVT_OFF  (KVK_OFF + 256*68)
#define PT_OFF   (KVT_OFF + 64*256)
#define RM_OFF   (PT_OFF + 64*68)
#define RL_OFF   (RM_OFF + 64)
#define RA_OFF   (RL_OFF + 64)
#define ATTN_SMEM_FLOATS (RA_OFF + 64)

__global__ void __launch_bounds__(256) attn_kernel(
    const float* __restrict__ q, const float* __restrict__ kv,
    const float* __restrict__ sink, float* __restrict__ o)
{
    extern __shared__ float smf[];
    float* Qs  = smf + QS_OFF;
    float* KVk = smf + KVK_OFF;
    float* KVt = smf + KVT_OFF;
    float* Pt  = smf + PT_OFF;
    float* rowm = smf + RM_OFF;
    float* rowl = smf + RL_OFF;
    float* rowa = smf + RA_OFF;

    const int qb = (int)(gridDim.x - 1 - blockIdx.x);
    const int h  = blockIdx.y;
    const int s0 = qb * 64;
    const int tid = threadIdx.x;
    const int tx = tid & 15, ty = tid >> 4;
    const int lr = tid >> 2, lq = tid & 3;

    #pragma unroll
    for (int j = 0; j < 16; j++) {
        int kq = lq + j * 4;
        float4 v = *(const float4*)&q[((size_t)(s0 + lr) * H_ + h) * D_ + kq * 4];
        Qs[(kq*4+0)*68 + lr] = v.x;
        Qs[(kq*4+1)*68 + lr] = v.y;
        Qs[(kq*4+2)*68 + lr] = v.z;
        Qs[(kq*4+3)*68 + lr] = v.w;
    }
    if (tid < 64) { rowm[tid] = -1e30f; rowl[tid] = 0.f; }

    float4 oa[4][4];
    #pragma unroll
    for (int i = 0; i < 4; i++)
        #pragma unroll
        for (int g = 0; g < 4; g++) oa[i][g] = make_float4(0.f,0.f,0.f,0.f);

    const int ntiles = qb + 1;
    for (int t0 = 0; t0 < ntiles; t0++) {
        __syncthreads();
        #pragma unroll
        for (int j = 0; j < 16; j++) {
            int kq = lq + j * 4;
            float4 v = *(const float4*)&kv[(size_t)(t0 * 64 + lr) * D_ + kq * 4];
            *(float4*)&KVt[lr * 256 + kq * 4] = v;
            KVk[(kq*4+0)*68 + lr] = v.x;
            KVk[(kq*4+1)*68 + lr] = v.y;
            KVk[(kq*4+2)*68 + lr] = v.z;
            KVk[(kq*4+3)*68 + lr] = v.w;
        }
        __syncthreads();

        float acc[4][4] = {};
        #pragma unroll 4
        for (int k = 0; k < 256; k++) {
            float4 a = *(const float4*)&Qs[k*68 + ty*4];
            float4 b = *(const float4*)&KVk[k*68 + tx*4];
            float ar[4] = {a.x, a.y, a.z, a.w};
            float br[4] = {b.x, b.y, b.z, b.w};
            #pragma unroll
            for (int i = 0; i < 4; i++)
                #pragma unroll
                for (int j = 0; j < 4; j++)
                    acc[i][j] += ar[i] * br[j];
        }
        #pragma unroll
        for (int j = 0; j < 4; j++) {
            int kt = t0 * 64 + tx * 4 + j;
            #pragma unroll
            for (int i = 0; i < 4; i++) {
                int sr = s0 + ty * 4 + i;
                float v = acc[i][j] * SCALE_;
                if (kt > sr) v = -1e30f;
                Pt[(tx*4+j)*68 + ty*4+i] = v;
            }
        }
        __syncthreads();

        {
            int r = tid >> 2, sub = tid & 3;
            float vals[16];
            float mloc = -1e30f;
            #pragma unroll
            for (int tt = 0; tt < 16; tt++) {
                vals[tt] = Pt[(sub*16+tt)*68 + r];
                mloc = fmaxf(mloc, vals[tt]);
            }
            mloc = fmaxf(mloc, __shfl_xor_sync(0xffffffffu, mloc, 1));
            mloc = fmaxf(mloc, __shfl_xor_sync(0xffffffffu, mloc, 2));
            float mold = rowm[r];
            float mnew = fmaxf(mold, mloc);
            float s = 0.f;
            #pragma unroll
            for (int tt = 0; tt < 16; tt++) {
                float e = __expf(vals[tt] - mnew);
                Pt[(sub*16+tt)*68 + r] = e;
                s += e;
            }
            s += __shfl_xor_sync(0xffffffffu, s, 1);
            s += __shfl_xor_sync(0xffffffffu, s, 2);
            if (sub == 0) {
                float alpha = __expf(mold - mnew);
                rowa[r] = alpha;
                rowl[r] = rowl[r] * alpha + s;
                rowm[r] = mnew;
            }
        }
        __syncthreads();

        float al[4];
        #pragma unroll
        for (int i = 0; i < 4; i++) al[i] = rowa[ty*4+i];
        #pragma unroll
        for (int i = 0; i < 4; i++)
            #pragma unroll
            for (int g = 0; g < 4; g++) {
                oa[i][g].x *= al[i]; oa[i][g].y *= al[i];
                oa[i][g].z *= al[i]; oa[i][g].w *= al[i];
            }
        #pragma unroll 2
        for (int t = 0; t < 64; t++) {
            float4 a = *(const float4*)&Pt[t*68 + ty*4];
            float ar[4] = {a.x, a.y, a.z, a.w};
            #pragma unroll
            for (int g = 0; g < 4; g++) {
                float4 b = *(const float4*)&KVt[t*256 + tx*4 + g*64];
                #pragma unroll
                for (int i = 0; i < 4; i++) {
                    oa[i][g].x += ar[i] * b.x;
                    oa[i][g].y += ar[i] * b.y;
                    oa[i][g].z += ar[i] * b.z;
                    oa[i][g].w += ar[i] * b.w;
                }
            }
        }
    }

    float sk = sink[h];
    #pragma unroll
    for (int i = 0; i < 4; i++) {
        int r = ty * 4 + i;
        float denom = rowl[r] + __expf(sk - rowm[r]);
        float inv = 1.f / denom;
        int sr = s0 + r;
        float* op = o + ((size_t)sr * H_ + h) * D_ + tx * 4;
        #pragma unroll
        for (int g = 0; g < 4; g++) {
            float4 v = make_float4(oa[i][g].x*inv, oa[i][g].y*inv,
                                   oa[i][g].z*inv, oa[i][g].w*inv);
            *(float4*)(op + g * 64) = v;
        }
    }
}

// ==================== conjugate RoPE ====================
__global__ void o_rope_conj(float* __restrict__ o, const float* __restrict__ freqs)
{
    int s = blockIdx.x, h = blockIdx.y;
    int i = threadIdx.x;
    float* p = o + ((size_t)s * H_ + h) * D_ + NOPE_;
    float f = freqs[s * RH_ + i];
    float c = cosf(f), sn = sinf(f);
    float x1 = p[2 * i], x2 = p[2 * i + 1];
    p[2 * i]     = x1 * c + x2 * sn;
    p[2 * i + 1] = x2 * c - x1 * sn;
}

// ==================== launch ====================
extern "C" void kernel_launch(void* const* d_in, const int* in_sizes, int n_in,
                              void* d_out, int out_size)
{
    const float* x         = (const float*)d_in[0];
    const float* freqs     = (const float*)d_in[1];
    const float* wq_a      = (const float*)d_in[2];
    const float* q_norm_w  = (const float*)d_in[3];
    const float* wq_b      = (const float*)d_in[4];
    const float* wkv       = (const float*)d_in[5];
    const float* kv_norm_w = (const float*)d_in[6];
    const float* wo_a_w    = (const float*)d_in[7];
    const float* wo_b      = (const float*)d_in[8];
    const float* attn_sink = (const float*)d_in[9];
    float* out = (float*)d_out;

    float *qa, *qbuf, *kvbuf, *obuf, *orbuf;
    cudaGetSymbolAddress((void**)&qa,    g_qa);
    cudaGetSymbolAddress((void**)&qbuf,  g_q);
    cudaGetSymbolAddress((void**)&kvbuf, g_kv);
    cudaGetSymbolAddress((void**)&obuf,  g_o);
    cudaGetSymbolAddress((void**)&orbuf, g_or);

    static int smem_set = 0;
    if (!smem_set) {
        cudaFuncSetAttribute(attn_kernel, cudaFuncAttributeMaxDynamicSharedMemorySize,
                             ATTN_SMEM_FLOATS * (int)sizeof(float));
        cudaFuncSetAttribute(gemm_wmma, cudaFuncAttributeMaxDynamicSharedMemorySize,
                             GW_SMEM);
        smem_set = 1;
    }

    dim3 blk(256);
    // q_a = x @ wq_a^T   [2048,1024], K=2048
    gemm_wmma<<<dim3(16, 8, 1), blk, GW_SMEM>>>(x, HID_, wq_a, HID_, qa, QL_, HID_, 0, 0, 0);
    // kv_raw = x @ wkv^T [2048,256], K=2048 (fp32, more CTAs)
    gemm_abt<<<dim3(32, 4), blk>>>(x, HID_, wkv, HID_, kvbuf, D_, HID_);
    // rms(q_a)
    rmsnorm_rows<<<S_, 256>>>(qa, q_norm_w, QL_);
    // q = q_a @ wq_b^T   [2048,4096], K=1024
    gemm_wmma<<<dim3(16, 32, 1), blk, GW_SMEM>>>(qa, QL_, wq_b, QL_, qbuf, H_ * D_, QL_, 0, 0, 0);
    // kv: rms + rope
    kvprep<<<S_, 256>>>(kvbuf, kv_norm_w, freqs);
    // q: head-norm + rope
    qprep<<<dim3(S_, H_), 256>>>(qbuf, freqs);
    // attention
    attn_kernel<<<dim3(S_ / 64, H_), blk, ATTN_SMEM_FLOATS * (int)sizeof(float)>>>(
        qbuf, kvbuf, attn_sink, obuf);
    // conj rope on o
    o_rope_conj<<<dim3(S_, H_), 32>>>(obuf, freqs);
    // grouped low-rank: z = 4 groups, [2048,512] each, K=1024
    gemm_wmma<<<dim3(16, 4, 4), blk, GW_SMEM>>>(obuf, H_ * D_, wo_a_w, 1024,
                                                orbuf, G_ * OR_, 1024,
                                                1024L, (long)OR_ * 1024L, (long)OR_);
    // out = o_r @ wo_b^T [2048,2048], K=2048
    gemm_wmma<<<dim3(16, 16, 1), blk, GW_SMEM>>>(orbuf, G_ * OR_, wo_b, HID_,
                                                 out, HID_, G_ * OR_, 0, 0, 0);
}

// round 11
// speedup vs baseline: 6.5153x; 1.2067x over previous
#include <cuda_runtime.h>
#include <cuda_bf16.h>
#include <mma.h>
#include <math.h>
#include <stdint.h>

using namespace nvcuda;

#define S_    2048
#define HID_  2048
#define H_    16
#define D_    256
#define NOPE_ 192
#define RH_   32
#define QL_   1024
#define OR_   512
#define G_    4
#define EPS_  1e-6f
#define SCALE_ 0.0625f

// -------- fp32 scratch --------
__device__ float g_qa[S_ * QL_];
__device__ float g_q[(size_t)S_ * H_ * D_];
__device__ float g_kv[S_ * D_];
__device__ float g_o[(size_t)S_ * H_ * D_];
__device__ float g_or[S_ * G_ * OR_];

// -------- bf16 hi/lo scratch --------
__device__ __nv_bfloat16 g_xh[S_ * HID_],        g_xl[S_ * HID_];
__device__ __nv_bfloat16 g_wqah[QL_ * HID_],     g_wqal[QL_ * HID_];
__device__ __nv_bfloat16 g_wqbh[H_ * D_ * QL_],  g_wqbl[H_ * D_ * QL_];
__device__ __nv_bfloat16 g_qah[S_ * QL_],        g_qal[S_ * QL_];
__device__ __nv_bfloat16 g_woah[G_ * OR_ * 1024], g_woal[G_ * OR_ * 1024];
__device__ __nv_bfloat16 g_wobh[HID_ * G_ * OR_], g_wobl[HID_ * G_ * OR_];
__device__ __nv_bfloat16 g_oh[(size_t)S_ * H_ * D_], g_ol[(size_t)S_ * H_ * D_];
__device__ __nv_bfloat16 g_orh[S_ * G_ * OR_],   g_orl[S_ * G_ * OR_];

__device__ __forceinline__ uint32_t b2u(__nv_bfloat162 h) {
    return *reinterpret_cast<uint32_t*>(&h);
}

// ==================== fp32 -> (hi, lo) bf16 conversion, 4 elems/thread ====================
__global__ void cvt_hilo(const float* __restrict__ in,
                         __nv_bfloat16* __restrict__ h,
                         __nv_bfloat16* __restrict__ l, int n4)
{
    int i = blockIdx.x * blockDim.x + threadIdx.x;
    if (i >= n4) return;
    float4 v = ((const float4*)in)[i];
    __nv_bfloat162 h01 = __floats2bfloat162_rn(v.x, v.y);
    __nv_bfloat162 h23 = __floats2bfloat162_rn(v.z, v.w);
    __nv_bfloat162 l01 = __floats2bfloat162_rn(
        v.x - __bfloat162float(__low2bfloat16(h01)),
        v.y - __bfloat162float(__high2bfloat16(h01)));
    __nv_bfloat162 l23 = __floats2bfloat162_rn(
        v.z - __bfloat162float(__low2bfloat16(h23)),
        v.w - __bfloat162float(__high2bfloat16(h23)));
    ((uint2*)h)[i] = make_uint2(b2u(h01), b2u(h23));
    ((uint2*)l)[i] = make_uint2(b2u(l01), b2u(l23));
}

// ==================== split-bf16 tensor GEMM: C[M,N] = A[M,K] * B[N,K]^T ====================
// A,B given as hi/lo bf16. 128x128 CTA tile, 8 warps 2x4 (64x32 warp tile).
#define BST 72
#define GBF_SMEM (4 * 128 * BST * 2)

__global__ void __launch_bounds__(256, 2) gemm_bfs(
    const __nv_bfloat16* __restrict__ Ah, const __nv_bfloat16* __restrict__ Al, int lda,
    const __nv_bfloat16* __restrict__ Bh, const __nv_bfloat16* __restrict__ Bl, int ldb,
    float* __restrict__ C, int ldc, int K,
    long sAz, long sBz, long sCz)
{
    extern __shared__ __nv_bfloat16 sb[];
    __nv_bfloat16* Ah_s = sb;
    __nv_bfloat16* Al_s = sb + 128 * BST;
    __nv_bfloat16* Bh_s = sb + 2 * 128 * BST;
    __nv_bfloat16* Bl_s = sb + 3 * 128 * BST;

    Ah += (size_t)blockIdx.z * sAz;  Al += (size_t)blockIdx.z * sAz;
    Bh += (size_t)blockIdx.z * sBz;  Bl += (size_t)blockIdx.z * sBz;
    C  += (size_t)blockIdx.z * sCz;

    const int tid = threadIdx.x;
    const int warp = tid >> 5;
    const int wm = warp & 1, wn = warp >> 1;

    wmma::fragment<wmma::accumulator, 16, 16, 16, float> acc[4][2];
    #pragma unroll
    for (int i = 0; i < 4; i++)
        #pragma unroll
        for (int j = 0; j < 2; j++)
            wmma::fill_fragment(acc[i][j], 0.0f);

    const int r  = tid >> 1;
    const int c0 = (tid & 1) * 32;
    const size_t aoff = (size_t)(blockIdx.x * 128 + r) * lda + c0;
    const size_t boff = (size_t)(blockIdx.y * 128 + r) * ldb + c0;
    const int sidx = r * BST + c0;

    const int nkc = K >> 6;
    for (int kc = 0; kc < nkc; kc++) {
        __syncthreads();
        {
            const uint4* gah = (const uint4*)(Ah + aoff + kc * 64);
            const uint4* gal = (const uint4*)(Al + aoff + kc * 64);
            const uint4* gbh = (const uint4*)(Bh + boff + kc * 64);
            const uint4* gbl = (const uint4*)(Bl + boff + kc * 64);
            #pragma unroll
            for (int j = 0; j < 4; j++) {
                *(uint4*)(Ah_s + sidx + j * 8) = gah[j];
                *(uint4*)(Al_s + sidx + j * 8) = gal[j];
                *(uint4*)(Bh_s + sidx + j * 8) = gbh[j];
                *(uint4*)(Bl_s + sidx + j * 8) = gbl[j];
            }
        }
        __syncthreads();

        #pragma unroll
        for (int ks = 0; ks < 4; ks++) {
            wmma::fragment<wmma::matrix_a, 16, 16, 16, __nv_bfloat16, wmma::row_major> ah[4];
            wmma::fragment<wmma::matrix_b, 16, 16, 16, __nv_bfloat16, wmma::col_major> bh[2];
            #pragma unroll
            for (int i = 0; i < 4; i++)
                wmma::load_matrix_sync(ah[i], Ah_s + (wm * 64 + i * 16) * BST + ks * 16, BST);
            #pragma unroll
            for (int j = 0; j < 2; j++)
                wmma::load_matrix_sync(bh[j], Bh_s + (wn * 32 + j * 16) * BST + ks * 16, BST);
            #pragma unroll
            for (int i = 0; i < 4; i++)
                #pragma unroll
                for (int j = 0; j < 2; j++)
                    wmma::mma_sync(acc[i][j], ah[i], bh[j], acc[i][j]);
            {
                wmma::fragment<wmma::matrix_b, 16, 16, 16, __nv_bfloat16, wmma::col_major> bl[2];
                #pragma unroll
                for (int j = 0; j < 2; j++)
                    wmma::load_matrix_sync(bl[j], Bl_s + (wn * 32 + j * 16) * BST + ks * 16, BST);
                #pragma unroll
                for (int i = 0; i < 4; i++)
                    #pragma unroll
                    for (int j = 0; j < 2; j++)
                        wmma::mma_sync(acc[i][j], ah[i], bl[j], acc[i][j]);
            }
            {
                wmma::fragment<wmma::matrix_a, 16, 16, 16, __nv_bfloat16, wmma::row_major> al[4];
                #pragma unroll
                for (int i = 0; i < 4; i++)
                    wmma::load_matrix_sync(al[i], Al_s + (wm * 64 + i * 16) * BST + ks * 16, BST);
                #pragma unroll
                for (int i = 0; i < 4; i++)
                    #pragma unroll
                    for (int j = 0; j < 2; j++)
                        wmma::mma_sync(acc[i][j], al[i], bh[j], acc[i][j]);
            }
        }
    }

    #pragma unroll
    for (int i = 0; i < 4; i++)
        #pragma unroll
        for (int j = 0; j < 2; j++) {
            float* Cp = C + (size_t)(blockIdx.x * 128 + wm * 64 + i * 16) * ldc
                          + blockIdx.y * 128 + wn * 32 + j * 16;
            wmma::store_matrix_sync(Cp, acc[i][j], ldc, wmma::mem_row_major);
        }
}

// ==================== small fp32 GEMM (64x64) for kv ====================
__global__ void __launch_bounds__(256) gemm_abt(
    const float* __restrict__ A, int lda,
    const float* __restrict__ B, int ldb,
    float* __restrict__ C, int ldc, int K)
{
    __shared__ float As[16][68];
    __shared__ float Bs[16][68];
    const int tid = threadIdx.x;
    const int tx = tid & 15, ty = tid >> 4;
    const int lr = tid >> 2, lq = tid & 3;
    const float* Ab = A + (size_t)(blockIdx.x * 64 + lr) * lda + lq * 4;
    const float* Bb = B + (size_t)(blockIdx.y * 64 + lr) * ldb + lq * 4;
    float acc[4][4] = {};
    for (int k0 = 0; k0 < K; k0 += 16) {
        float4 av = *(const float4*)(Ab + k0);
        float4 bv = *(const float4*)(Bb + k0);
        As[lq*4+0][lr] = av.x; As[lq*4+1][lr] = av.y;
        As[lq*4+2][lr] = av.z; As[lq*4+3][lr] = av.w;
        Bs[lq*4+0][lr] = bv.x; Bs[lq*4+1][lr] = bv.y;
        Bs[lq*4+2][lr] = bv.z; Bs[lq*4+3][lr] = bv.w;
        __syncthreads();
        #pragma unroll
        for (int k = 0; k < 16; k++) {
            float4 a = *(const float4*)&As[k][ty * 4];
            float4 b = *(const float4*)&Bs[k][tx * 4];
            float ar[4] = {a.x, a.y, a.z, a.w};
            float br[4] = {b.x, b.y, b.z, b.w};
            #pragma unroll
            for (int i = 0; i < 4; i++)
                #pragma unroll
                for (int j = 0; j < 4; j++)
                    acc[i][j] += ar[i] * br[j];
        }
        __syncthreads();
    }
    float* Cp = C + (size_t)(blockIdx.x * 64 + ty * 4) * ldc + blockIdx.y * 64 + tx * 4;
    #pragma unroll
    for (int i = 0; i < 4; i++) {
        float4 v = make_float4(acc[i][0], acc[i][1], acc[i][2], acc[i][3]);
        *(float4*)(Cp + (size_t)i * ldc) = v;
    }
}

// ==================== RMS norm (L=1024) emitting hi/lo bf16 ====================
__global__ void rmsnorm_hilo(const float* __restrict__ x, const float* __restrict__ w,
                             __nv_bfloat16* __restrict__ h, __nv_bfloat16* __restrict__ l)
{
    int row = blockIdx.x;
    int t = threadIdx.x;   // 256
    const float4* p = (const float4*)(x + (size_t)row * QL_);
    float4 v = p[t];
    float ss = v.x * v.x + v.y * v.y + v.z * v.z + v.w * v.w;
    __shared__ float red[8];
    #pragma unroll
    for (int o = 16; o; o >>= 1) ss += __shfl_xor_sync(0xffffffffu, ss, o);
    if ((t & 31) == 0) red[t >> 5] = ss;
    __syncthreads();
    if (t < 32) {
        float r = (t < 8) ? red[t] : 0.f;
        #pragma unroll
        for (int o = 4; o; o >>= 1) r += __shfl_xor_sync(0xffffffffu, r, o);
        if (t == 0) red[0] = r;
    }
    __syncthreads();
    float inv = rsqrtf(red[0] / (float)QL_ + EPS_);
    float4 wv = ((const float4*)w)[t];
    float4 o4 = make_float4(v.x * inv * wv.x, v.y * inv * wv.y,
                            v.z * inv * wv.z, v.w * inv * wv.w);
    __nv_bfloat162 h01 = __floats2bfloat162_rn(o4.x, o4.y);
    __nv_bfloat162 h23 = __floats2bfloat162_rn(o4.z, o4.w);
    __nv_bfloat162 l01 = __floats2bfloat162_rn(
        o4.x - __bfloat162float(__low2bfloat16(h01)),
        o4.y - __bfloat162float(__high2bfloat16(h01)));
    __nv_bfloat162 l23 = __floats2bfloat162_rn(
        o4.z - __bfloat162float(__low2bfloat16(h23)),
        o4.w - __bfloat162float(__high2bfloat16(h23)));
    ((uint2*)(h + (size_t)row * QL_))[t] = make_uint2(b2u(h01), b2u(h23));
    ((uint2*)(l + (size_t)row * QL_))[t] = make_uint2(b2u(l01), b2u(l23));
}

// ==================== q prep ====================
__global__ void qprep(float* __restrict__ q, const float* __restrict__ freqs)
{
    int s = blockIdx.x, h = blockIdx.y;
    float* p = q + ((size_t)s * H_ + h) * D_;
    int t = threadIdx.x;
    float v = p[t];
    float ss = v * v;
    __shared__ float red[8];
    __shared__ float rowbuf[D_];
    #pragma unroll
    for (int o = 16; o; o >>= 1) ss += __shfl_xor_sync(0xffffffffu, ss, o);
    if ((t & 31) == 0) red[t >> 5] = ss;
    __syncthreads();
    if (t < 32) {
        float r = (t < 8) ? red[t] : 0.f;
        #pragma unroll
        for (int o = 4; o; o >>= 1) r += __shfl_xor_sync(0xffffffffu, r, o);
        if (t == 0) red[0] = r;
    }
    __syncthreads();
    float inv = rsqrtf(red[0] / (float)D_ + EPS_);
    v *= inv;
    rowbuf[t] = v;
    __syncthreads();
    float outv = v;
    if (t >= NOPE_) {
        int i = (t - NOPE_) >> 1;
        float f = freqs[s * RH_ + i];
        float c = cosf(f), sn = sinf(f);
        float x1 = rowbuf[NOPE_ + 2 * i], x2 = rowbuf[NOPE_ + 2 * i + 1];
        outv = ((t & 1) == 0) ? (x1 * c - x2 * sn) : (x1 * sn + x2 * c);
    }
    p[t] = outv;
}

// ==================== kv prep ====================
__global__ void kvprep(float* __restrict__ kv, const float* __restrict__ w,
                       const float* __restrict__ freqs)
{
    int s = blockIdx.x;
    float* p = kv + (size_t)s * D_;
    int t = threadIdx.x;
    float v = p[t];
    float ss = v * v;
    __shared__ float red[8];
    __shared__ float rowbuf[D_];
    #pragma unroll
    for (int o = 16; o; o >>= 1) ss += __shfl_xor_sync(0xffffffffu, ss, o);
    if ((t & 31) == 0) red[t >> 5] = ss;
    __syncthreads();
    if (t < 32) {
        float r = (t < 8) ? red[t] : 0.f;
        #pragma unroll
        for (int o = 4; o; o >>= 1) r += __shfl_xor_sync(0xffffffffu, r, o);
        if (t == 0) red[0] = r;
    }
    __syncthreads();
    float inv = rsqrtf(red[0] / (float)D_ + EPS_);
    v = v * inv * w[t];
    rowbuf[t] = v;
    __syncthreads();
    float outv = v;
    if (t >= NOPE_) {
        int i = (t - NOPE_) >> 1;
        float f = freqs[s * RH_ + i];
        float c = cosf(f), sn = sinf(f);
        float x1 = rowbuf[NOPE_ + 2 * i], x2 = rowbuf[NOPE_ + 2 * i + 1];
        outv = ((t & 1) == 0) ? (x1 * c - x2 * sn) : (x1 * sn + x2 * c);
    }
    p[t] = outv;
}

// ==================== flash attention (fp32) ====================
#define QS_OFF   0
#define KVK_OFF  (QS_OFF + 256*68)
#define KVT_OFF  (KVK_OFF + 256*68)
#define PT_OFF   (KVT_OFF + 64*256)
#define RM_OFF   (PT_OFF + 64*68)
#define RL_OFF   (RM_OFF + 64)
#define RA_OFF   (RL_OFF + 64)
#define ATTN_SMEM_FLOATS (RA_OFF + 64)

__global__ void __launch_bounds__(256) attn_kernel(
    const float* __restrict__ q, const float* __restrict__ kv,
    const float* __restrict__ sink, float* __restrict__ o)
{
    extern __shared__ float smf[];
    float* Qs  = smf + QS_OFF;
    float* KVk = smf + KVK_OFF;
    float* KVt = smf + KVT_OFF;
    float* Pt  = smf + PT_OFF;
    float* rowm = smf + RM_OFF;
    float* rowl = smf + RL_OFF;
    float* rowa = smf + RA_OFF;

    const int qb = (int)(gridDim.x - 1 - blockIdx.x);
    const int h  = blockIdx.y;
    const int s0 = qb * 64;
    const int tid = threadIdx.x;
    const int tx = tid & 15, ty = tid >> 4;
    const int lr = tid >> 2, lq = tid & 3;

    #pragma unroll
    for (int j = 0; j < 16; j++) {
        int kq = lq + j * 4;
        float4 v = *(const float4*)&q[((size_t)(s0 + lr) * H_ + h) * D_ + kq * 4];
        Qs[(kq*4+0)*68 + lr] = v.x;
        Qs[(kq*4+1)*68 + lr] = v.y;
        Qs[(kq*4+2)*68 + lr] = v.z;
        Qs[(kq*4+3)*68 + lr] = v.w;
    }
    if (tid < 64) { rowm[tid] = -1e30f; rowl[tid] = 0.f; }

    float4 oa[4][4];
    #pragma unroll
    for (int i = 0; i < 4; i++)
        #pragma unroll
        for (int g = 0; g < 4; g++) oa[i][g] = make_float4(0.f,0.f,0.f,0.f);

    const int ntiles = qb + 1;
    for (int t0 = 0; t0 < ntiles; t0++) {
        __syncthreads();
        #pragma unroll
        for (int j = 0; j < 16; j++) {
            int kq = lq + j * 4;
            float4 v = *(const float4*)&kv[(size_t)(t0 * 64 + lr) * D_ + kq * 4];
            *(float4*)&KVt[lr * 256 + kq * 4] = v;
            KVk[(kq*4+0)*68 + lr] = v.x;
            KVk[(kq*4+1)*68 + lr] = v.y;
            KVk[(kq*4+2)*68 + lr] = v.z;
            KVk[(kq*4+3)*68 + lr] = v.w;
        }
        __syncthreads();

        float acc[4][4] = {};
        #pragma unroll 4
        for (int k = 0; k < 256; k++) {
            float4 a = *(const float4*)&Qs[k*68 + ty*4];
            float4 b = *(const float4*)&KVk[k*68 + tx*4];
            float ar[4] = {a.x, a.y, a.z, a.w};
            float br[4] = {b.x, b.y, b.z, b.w};
            #pragma unroll
            for (int i = 0; i < 4; i++)
                #pragma unroll
                for (int j = 0; j < 4; j++)
                    acc[i][j] += ar[i] * br[j];
        }
        #pragma unroll
        for (int j = 0; j < 4; j++) {
            int kt = t0 * 64 + tx * 4 + j;
            #pragma unroll
            for (int i = 0; i < 4; i++) {
                int sr = s0 + ty * 4 + i;
                float v = acc[i][j] * SCALE_;
                if (kt > sr) v = -1e30f;
                Pt[(tx*4+j)*68 + ty*4+i] = v;
            }
        }
        __syncthreads();

        {
            int r = tid >> 2, sub = tid & 3;
            float vals[16];
            float mloc = -1e30f;
            #pragma unroll
            for (int tt = 0; tt < 16; tt++) {
                vals[tt] = Pt[(sub*16+tt)*68 + r];
                mloc = fmaxf(mloc, vals[tt]);
            }
            mloc = fmaxf(mloc, __shfl_xor_sync(0xffffffffu, mloc, 1));
            mloc = fmaxf(mloc, __shfl_xor_sync(0xffffffffu, mloc, 2));
            float mold = rowm[r];
            float mnew = fmaxf(mold, mloc);
            float s = 0.f;
            #pragma unroll
            for (int tt = 0; tt < 16; tt++) {
                float e = __expf(vals[tt] - mnew);
                Pt[(sub*16+tt)*68 + r] = e;
                s += e;
            }
            s += __shfl_xor_sync(0xffffffffu, s, 1);
            s += __shfl_xor_sync(0xffffffffu, s, 2);
            if (sub == 0) {
                float alpha = __expf(mold - mnew);
                rowa[r] = alpha;
                rowl[r] = rowl[r] * alpha + s;
                rowm[r] = mnew;
            }
        }
        __syncthreads();

        float al[4];
        #pragma unroll
        for (int i = 0; i < 4; i++) al[i] = rowa[ty*4+i];
        #pragma unroll
        for (int i = 0; i < 4; i++)
            #pragma unroll
            for (int g = 0; g < 4; g++) {
                oa[i][g].x *= al[i]; oa[i][g].y *= al[i];
                oa[i][g].z *= al[i]; oa[i][g].w *= al[i];
            }
        #pragma unroll 2
        for (int t = 0; t < 64; t++) {
            float4 a = *(const float4*)&Pt[t*68 + ty*4];
            float ar[4] = {a.x, a.y, a.z, a.w};
            #pragma unroll
            for (int g = 0; g < 4; g++) {
                float4 b = *(const float4*)&KVt[t*256 + tx*4 + g*64];
                #pragma unroll
                for (int i = 0; i < 4; i++) {
                    oa[i][g].x += ar[i] * b.x;
                    oa[i][g].y += ar[i] * b.y;
                    oa[i][g].z += ar[i] * b.z;
                    oa[i][g].w += ar[i] * b.w;
                }
            }
        }
    }

    float sk = sink[h];
    #pragma unroll
    for (int i = 0; i < 4; i++) {
        int r = ty * 4 + i;
        float denom = rowl[r] + __expf(sk - rowm[r]);
        float inv = 1.f / denom;
        int sr = s0 + r;
        float* op = o + ((size_t)sr * H_ + h) * D_ + tx * 4;
        #pragma unroll
        for (int g = 0; g < 4; g++) {
            float4 v = make_float4(oa[i][g].x*inv, oa[i][g].y*inv,
                                   oa[i][g].z*inv, oa[i][g].w*inv);
            *(float4*)(op + g * 64) = v;
        }
    }
}

// ==================== conjugate RoPE ====================
__global__ void o_rope_conj(float* __restrict__ o, const float* __restrict__ freqs)
{
    int s = blockIdx.x, h = blockIdx.y;
    int i = threadIdx.x;
    float* p = o + ((size_t)s * H_ + h) * D_ + NOPE_;
    float f = freqs[s * RH_ + i];
    float c = cosf(f), sn = sinf(f);
    float x1 = p[2 * i], x2 = p[2 * i + 1];
    p[2 * i]     = x1 * c + x2 * sn;
    p[2 * i + 1] = x2 * c - x1 * sn;
}

// ==================== launch ====================
extern "C" void kernel_launch(void* const* d_in, const int* in_sizes, int n_in,
                              void* d_out, int out_size)
{
    const float* x         = (const float*)d_in[0];
    const float* freqs     = (const float*)d_in[1];
    const float* wq_a      = (const float*)d_in[2];
    const float* q_norm_w  = (const float*)d_in[3];
    const float* wq_b      = (const float*)d_in[4];
    const float* wkv       = (const float*)d_in[5];
    const float* kv_norm_w = (const float*)d_in[6];
    const float* wo_a_w    = (const float*)d_in[7];
    const float* wo_b      = (const float*)d_in[8];
    const float* attn_sink = (const float*)d_in[9];
    float* out = (float*)d_out;

    float *qa, *qbuf, *kvbuf, *obuf, *orbuf;
    cudaGetSymbolAddress((void**)&qa,    g_qa);
    cudaGetSymbolAddress((void**)&qbuf,  g_q);
    cudaGetSymbolAddress((void**)&kvbuf, g_kv);
    cudaGetSymbolAddress((void**)&obuf,  g_o);
    cudaGetSymbolAddress((void**)&orbuf, g_or);

    __nv_bfloat16 *xh, *xl, *wqah, *wqal, *wqbh, *wqbl, *qah, *qal;
    __nv_bfloat16 *woah, *woal, *wobh, *wobl, *oh, *ol, *orh, *orl;
    cudaGetSymbolAddress((void**)&xh, g_xh);     cudaGetSymbolAddress((void**)&xl, g_xl);
    cudaGetSymbolAddress((void**)&wqah, g_wqah); cudaGetSymbolAddress((void**)&wqal, g_wqal);
    cudaGetSymbolAddress((void**)&wqbh, g_wqbh); cudaGetSymbolAddress((void**)&wqbl, g_wqbl);
    cudaGetSymbolAddress((void**)&qah, g_qah);   cudaGetSymbolAddress((void**)&qal, g_qal);
    cudaGetSymbolAddress((void**)&woah, g_woah); cudaGetSymbolAddress((void**)&woal, g_woal);
    cudaGetSymbolAddress((void**)&wobh, g_wobh); cudaGetSymbolAddress((void**)&wobl, g_wobl);
    cudaGetSymbolAddress((void**)&oh, g_oh);     cudaGetSymbolAddress((void**)&ol, g_ol);
    cudaGetSymbolAddress((void**)&orh, g_orh);   cudaGetSymbolAddress((void**)&orl, g_orl);

    static int smem_set = 0;
    if (!smem_set) {
        cudaFuncSetAttribute(attn_kernel, cudaFuncAttributeMaxDynamicSharedMemorySize,
                             ATTN_SMEM_FLOATS * (int)sizeof(float));
        cudaFuncSetAttribute(gemm_bfs, cudaFuncAttributeMaxDynamicSharedMemorySize,
                             GBF_SMEM);
        smem_set = 1;
    }

    dim3 blk(256);
    // ---- conversions (inputs + weights) ----
    cvt_hilo<<<(S_*HID_/4 + 255)/256, 256>>>(x,      xh,   xl,   S_*HID_/4);
    cvt_hilo<<<(QL_*HID_/4 + 255)/256, 256>>>(wq_a,  wqah, wqal, QL_*HID_/4);
    cvt_hilo<<<(H_*D_*QL_/4 + 255)/256, 256>>>(wq_b, wqbh, wqbl, H_*D_*QL_/4);
    cvt_hilo<<<(G_*OR_*1024/4 + 255)/256, 256>>>(wo_a_w, woah, woal, G_*OR_*1024/4);
    cvt_hilo<<<(HID_*G_*OR_/4 + 255)/256, 256>>>(wo_b, wobh, wobl, HID_*G_*OR_/4);

    // q_a = x @ wq_a^T   [2048,1024], K=2048
    gemm_bfs<<<dim3(16, 8, 1), blk, GBF_SMEM>>>(xh, xl, HID_, wqah, wqal, HID_,
                                                qa, QL_, HID_, 0, 0, 0);
    // kv_raw = x @ wkv^T [2048,256], K=2048 (fp32)
    gemm_abt<<<dim3(32, 4), blk>>>(x, HID_, wkv, HID_, kvbuf, D_, HID_);
    // rms(q_a) -> hi/lo
    rmsnorm_hilo<<<S_, 256>>>(qa, q_norm_w, qah, qal);
    // q = q_a @ wq_b^T   [2048,4096], K=1024
    gemm_bfs<<<dim3(16, 32, 1), blk, GBF_SMEM>>>(qah, qal, QL_, wqbh, wqbl, QL_,
                                                 qbuf, H_ * D_, QL_, 0, 0, 0);
    // kv: rms + rope
    kvprep<<<S_, 256>>>(kvbuf, kv_norm_w, freqs);
    // q: head-norm + rope
    qprep<<<dim3(S_, H_), 256>>>(qbuf, freqs);
    // attention
    attn_kernel<<<dim3(S_ / 64, H_), blk, ATTN_SMEM_FLOATS * (int)sizeof(float)>>>(
        qbuf, kvbuf, attn_sink, obuf);
    // conj rope on o
    o_rope_conj<<<dim3(S_, H_), 32>>>(obuf, freqs);
    // o -> hi/lo
    cvt_hilo<<<((int)((size_t)S_*H_*D_/4) + 255)/256, 256>>>(obuf, oh, ol, (int)((size_t)S_*H_*D_/4));
    // grouped low-rank: z = 4 groups, [2048,512] each, K=1024
    gemm_bfs<<<dim3(16, 4, 4), blk, GBF_SMEM>>>(oh, ol, H_ * D_, woah, woal, 1024,
                                                orbuf, G_ * OR_, 1024,
                                                1024L, (long)OR_ * 1024L, (long)OR_);
    // o_r -> hi/lo
    cvt_hilo<<<(S_*G_*OR_/4 + 255)/256, 256>>>(orbuf, orh, orl, S_*G_*OR_/4);
    // out = o_r @ wo_b^T [2048,2048], K=2048
    gemm_bfs<<<dim3(16, 16, 1), blk, GBF_SMEM>>>(orh, orl, G_ * OR_, wobh, wobl, HID_,
                                                 out, HID_, G_ * OR_, 0, 0, 0);
}

// round 12
// speedup vs baseline: 8.4141x; 1.2914x over previous
#include <cuda_runtime.h>
#include <cuda_bf16.h>
#include <mma.h>
#include <math.h>
#include <stdint.h>

using namespace nvcuda;

#define S_    2048
#define HID_  2048
#define H_    16
#define D_    256
#define NOPE_ 192
#define RH_   32
#define QL_   1024
#define OR_   512
#define G_    4
#define EPS_  1e-6f
#define SCALE_ 0.0625f

// -------- fp32 scratch --------
__device__ float g_qa[S_ * QL_];
__device__ float g_q[(size_t)S_ * H_ * D_];
__device__ float g_kv[S_ * D_];
__device__ float g_o[(size_t)S_ * H_ * D_];
__device__ float g_or[S_ * G_ * OR_];

// -------- bf16 hi/lo scratch --------
__device__ __nv_bfloat16 g_xh[S_ * HID_],        g_xl[S_ * HID_];
__device__ __nv_bfloat16 g_wqah[QL_ * HID_],     g_wqal[QL_ * HID_];
__device__ __nv_bfloat16 g_wqbh[H_ * D_ * QL_],  g_wqbl[H_ * D_ * QL_];
__device__ __nv_bfloat16 g_qah[S_ * QL_],        g_qal[S_ * QL_];
__device__ __nv_bfloat16 g_woah[G_ * OR_ * 1024], g_woal[G_ * OR_ * 1024];
__device__ __nv_bfloat16 g_wobh[HID_ * G_ * OR_], g_wobl[HID_ * G_ * OR_];
__device__ __nv_bfloat16 g_oh[(size_t)S_ * H_ * D_], g_ol[(size_t)S_ * H_ * D_];
__device__ __nv_bfloat16 g_orh[S_ * G_ * OR_],   g_orl[S_ * G_ * OR_];
// attention bf16 operands
__device__ __nv_bfloat16 g_qh[(size_t)S_ * H_ * D_], g_ql2[(size_t)S_ * H_ * D_];
__device__ __nv_bfloat16 g_kvh[S_ * D_],         g_kvl[S_ * D_];

__device__ __forceinline__ uint32_t b2u(__nv_bfloat162 h) {
    return *reinterpret_cast<uint32_t*>(&h);
}

// ==================== fp32 -> (hi, lo) bf16 conversion ====================
__global__ void cvt_hilo(const float* __restrict__ in,
                         __nv_bfloat16* __restrict__ h,
                         __nv_bfloat16* __restrict__ l, int n4)
{
    int i = blockIdx.x * blockDim.x + threadIdx.x;
    if (i >= n4) return;
    float4 v = ((const float4*)in)[i];
    __nv_bfloat162 h01 = __floats2bfloat162_rn(v.x, v.y);
    __nv_bfloat162 h23 = __floats2bfloat162_rn(v.z, v.w);
    __nv_bfloat162 l01 = __floats2bfloat162_rn(
        v.x - __bfloat162float(__low2bfloat16(h01)),
        v.y - __bfloat162float(__high2bfloat16(h01)));
    __nv_bfloat162 l23 = __floats2bfloat162_rn(
        v.z - __bfloat162float(__low2bfloat16(h23)),
        v.w - __bfloat162float(__high2bfloat16(h23)));
    ((uint2*)h)[i] = make_uint2(b2u(h01), b2u(h23));
    ((uint2*)l)[i] = make_uint2(b2u(l01), b2u(l23));
}

// ==================== split-bf16 tensor GEMM ====================
#define BST 72
#define GBF_SMEM (4 * 128 * BST * 2)

__global__ void __launch_bounds__(256, 2) gemm_bfs(
    const __nv_bfloat16* __restrict__ Ah, const __nv_bfloat16* __restrict__ Al, int lda,
    const __nv_bfloat16* __restrict__ Bh, const __nv_bfloat16* __restrict__ Bl, int ldb,
    float* __restrict__ C, int ldc, int K,
    long sAz, long sBz, long sCz)
{
    extern __shared__ __nv_bfloat16 sb[];
    __nv_bfloat16* Ah_s = sb;
    __nv_bfloat16* Al_s = sb + 128 * BST;
    __nv_bfloat16* Bh_s = sb + 2 * 128 * BST;
    __nv_bfloat16* Bl_s = sb + 3 * 128 * BST;

    Ah += (size_t)blockIdx.z * sAz;  Al += (size_t)blockIdx.z * sAz;
    Bh += (size_t)blockIdx.z * sBz;  Bl += (size_t)blockIdx.z * sBz;
    C  += (size_t)blockIdx.z * sCz;

    const int tid = threadIdx.x;
    const int warp = tid >> 5;
    const int wm = warp & 1, wn = warp >> 1;

    wmma::fragment<wmma::accumulator, 16, 16, 16, float> acc[4][2];
    #pragma unroll
    for (int i = 0; i < 4; i++)
        #pragma unroll
        for (int j = 0; j < 2; j++)
            wmma::fill_fragment(acc[i][j], 0.0f);

    const int r  = tid >> 1;
    const int c0 = (tid & 1) * 32;
    const size_t aoff = (size_t)(blockIdx.x * 128 + r) * lda + c0;
    const size_t boff = (size_t)(blockIdx.y * 128 + r) * ldb + c0;
    const int sidx = r * BST + c0;

    const int nkc = K >> 6;
    for (int kc = 0; kc < nkc; kc++) {
        __syncthreads();
        {
            const uint4* gah = (const uint4*)(Ah + aoff + kc * 64);
            const uint4* gal = (const uint4*)(Al + aoff + kc * 64);
            const uint4* gbh = (const uint4*)(Bh + boff + kc * 64);
            const uint4* gbl = (const uint4*)(Bl + boff + kc * 64);
            #pragma unroll
            for (int j = 0; j < 4; j++) {
                *(uint4*)(Ah_s + sidx + j * 8) = gah[j];
                *(uint4*)(Al_s + sidx + j * 8) = gal[j];
                *(uint4*)(Bh_s + sidx + j * 8) = gbh[j];
                *(uint4*)(Bl_s + sidx + j * 8) = gbl[j];
            }
        }
        __syncthreads();

        #pragma unroll
        for (int ks = 0; ks < 4; ks++) {
            wmma::fragment<wmma::matrix_a, 16, 16, 16, __nv_bfloat16, wmma::row_major> ah[4];
            wmma::fragment<wmma::matrix_b, 16, 16, 16, __nv_bfloat16, wmma::col_major> bh[2];
            #pragma unroll
            for (int i = 0; i < 4; i++)
                wmma::load_matrix_sync(ah[i], Ah_s + (wm * 64 + i * 16) * BST + ks * 16, BST);
            #pragma unroll
            for (int j = 0; j < 2; j++)
                wmma::load_matrix_sync(bh[j], Bh_s + (wn * 32 + j * 16) * BST + ks * 16, BST);
            #pragma unroll
            for (int i = 0; i < 4; i++)
                #pragma unroll
                for (int j = 0; j < 2; j++)
                    wmma::mma_sync(acc[i][j], ah[i], bh[j], acc[i][j]);
            {
                wmma::fragment<wmma::matrix_b, 16, 16, 16, __nv_bfloat16, wmma::col_major> bl[2];
                #pragma unroll
                for (int j = 0; j < 2; j++)
                    wmma::load_matrix_sync(bl[j], Bl_s + (wn * 32 + j * 16) * BST + ks * 16, BST);
                #pragma unroll
                for (int i = 0; i < 4; i++)
                    #pragma unroll
                    for (int j = 0; j < 2; j++)
                        wmma::mma_sync(acc[i][j], ah[i], bl[j], acc[i][j]);
            }
            {
                wmma::fragment<wmma::matrix_a, 16, 16, 16, __nv_bfloat16, wmma::row_major> al[4];
                #pragma unroll
                for (int i = 0; i < 4; i++)
                    wmma::load_matrix_sync(al[i], Al_s + (wm * 64 + i * 16) * BST + ks * 16, BST);
                #pragma unroll
                for (int i = 0; i < 4; i++)
                    #pragma unroll
                    for (int j = 0; j < 2; j++)
                        wmma::mma_sync(acc[i][j], al[i], bh[j], acc[i][j]);
            }
        }
    }

    #pragma unroll
    for (int i = 0; i < 4; i++)
        #pragma unroll
        for (int j = 0; j < 2; j++) {
            float* Cp = C + (size_t)(blockIdx.x * 128 + wm * 64 + i * 16) * ldc
                          + blockIdx.y * 128 + wn * 32 + j * 16;
            wmma::store_matrix_sync(Cp, acc[i][j], ldc, wmma::mem_row_major);
        }
}

// ==================== small fp32 GEMM (64x64) for kv ====================
__global__ void __launch_bounds__(256) gemm_abt(
    const float* __restrict__ A, int lda,
    const float* __restrict__ B, int ldb,
    float* __restrict__ C, int ldc, int K)
{
    __shared__ float As[16][68];
    __shared__ float Bs[16][68];
    const int tid = threadIdx.x;
    const int tx = tid & 15, ty = tid >> 4;
    const int lr = tid >> 2, lq = tid & 3;
    const float* Ab = A + (size_t)(blockIdx.x * 64 + lr) * lda + lq * 4;
    const float* Bb = B + (size_t)(blockIdx.y * 64 + lr) * ldb + lq * 4;
    float acc[4][4] = {};
    for (int k0 = 0; k0 < K; k0 += 16) {
        float4 av = *(const float4*)(Ab + k0);
        float4 bv = *(const float4*)(Bb + k0);
        As[lq*4+0][lr] = av.x; As[lq*4+1][lr] = av.y;
        As[lq*4+2][lr] = av.z; As[lq*4+3][lr] = av.w;
        Bs[lq*4+0][lr] = bv.x; Bs[lq*4+1][lr] = bv.y;
        Bs[lq*4+2][lr] = bv.z; Bs[lq*4+3][lr] = bv.w;
        __syncthreads();
        #pragma unroll
        for (int k = 0; k < 16; k++) {
            float4 a = *(const float4*)&As[k][ty * 4];
            float4 b = *(const float4*)&Bs[k][tx * 4];
            float ar[4] = {a.x, a.y, a.z, a.w};
            float br[4] = {b.x, b.y, b.z, b.w};
            #pragma unroll
            for (int i = 0; i < 4; i++)
                #pragma unroll
                for (int j = 0; j < 4; j++)
                    acc[i][j] += ar[i] * br[j];
        }
        __syncthreads();
    }
    float* Cp = C + (size_t)(blockIdx.x * 64 + ty * 4) * ldc + blockIdx.y * 64 + tx * 4;
    #pragma unroll
    for (int i = 0; i < 4; i++) {
        float4 v = make_float4(acc[i][0], acc[i][1], acc[i][2], acc[i][3]);
        *(float4*)(Cp + (size_t)i * ldc) = v;
    }
}

// ==================== RMS norm (L=1024) emitting hi/lo bf16 ====================
__global__ void rmsnorm_hilo(const float* __restrict__ x, const float* __restrict__ w,
                             __nv_bfloat16* __restrict__ h, __nv_bfloat16* __restrict__ l)
{
    int row = blockIdx.x;
    int t = threadIdx.x;
    const float4* p = (const float4*)(x + (size_t)row * QL_);
    float4 v = p[t];
    float ss = v.x * v.x + v.y * v.y + v.z * v.z + v.w * v.w;
    __shared__ float red[8];
    #pragma unroll
    for (int o = 16; o; o >>= 1) ss += __shfl_xor_sync(0xffffffffu, ss, o);
    if ((t & 31) == 0) red[t >> 5] = ss;
    __syncthreads();
    if (t < 32) {
        float r = (t < 8) ? red[t] : 0.f;
        #pragma unroll
        for (int o = 4; o; o >>= 1) r += __shfl_xor_sync(0xffffffffu, r, o);
        if (t == 0) red[0] = r;
    }
    __syncthreads();
    float inv = rsqrtf(red[0] / (float)QL_ + EPS_);
    float4 wv = ((const float4*)w)[t];
    float4 o4 = make_float4(v.x * inv * wv.x, v.y * inv * wv.y,
                            v.z * inv * wv.z, v.w * inv * wv.w);
    __nv_bfloat162 h01 = __floats2bfloat162_rn(o4.x, o4.y);
    __nv_bfloat162 h23 = __floats2bfloat162_rn(o4.z, o4.w);
    __nv_bfloat162 l01 = __floats2bfloat162_rn(
        o4.x - __bfloat162float(__low2bfloat16(h01)),
        o4.y - __bfloat162float(__high2bfloat16(h01)));
    __nv_bfloat162 l23 = __floats2bfloat162_rn(
        o4.z - __bfloat162float(__low2bfloat16(h23)),
        o4.w - __bfloat162float(__high2bfloat16(h23)));
    ((uint2*)(h + (size_t)row * QL_))[t] = make_uint2(b2u(h01), b2u(h23));
    ((uint2*)(l + (size_t)row * QL_))[t] = make_uint2(b2u(l01), b2u(l23));
}

// ==================== q prep: head-norm + RoPE -> bf16 hi/lo ====================
__global__ void qprep(const float* __restrict__ q, const float* __restrict__ freqs,
                      __nv_bfloat16* __restrict__ qh, __nv_bfloat16* __restrict__ ql)
{
    int s = blockIdx.x, h = blockIdx.y;
    const float* p = q + ((size_t)s * H_ + h) * D_;
    int t = threadIdx.x;
    float v = p[t];
    float ss = v * v;
    __shared__ float red[8];
    __shared__ float rowbuf[D_];
    #pragma unroll
    for (int o = 16; o; o >>= 1) ss += __shfl_xor_sync(0xffffffffu, ss, o);
    if ((t & 31) == 0) red[t >> 5] = ss;
    __syncthreads();
    if (t < 32) {
        float r = (t < 8) ? red[t] : 0.f;
        #pragma unroll
        for (int o = 4; o; o >>= 1) r += __shfl_xor_sync(0xffffffffu, r, o);
        if (t == 0) red[0] = r;
    }
    __syncthreads();
    float inv = rsqrtf(red[0] / (float)D_ + EPS_);
    v *= inv;
    rowbuf[t] = v;
    __syncthreads();
    float outv = v;
    if (t >= NOPE_) {
        int i = (t - NOPE_) >> 1;
        float f = freqs[s * RH_ + i];
        float c = cosf(f), sn = sinf(f);
        float x1 = rowbuf[NOPE_ + 2 * i], x2 = rowbuf[NOPE_ + 2 * i + 1];
        outv = ((t & 1) == 0) ? (x1 * c - x2 * sn) : (x1 * sn + x2 * c);
    }
    __nv_bfloat16 hi = __float2bfloat16(outv);
    __nv_bfloat16 lo = __float2bfloat16(outv - __bfloat162float(hi));
    size_t idx = ((size_t)s * H_ + h) * D_ + t;
    qh[idx] = hi;
    ql[idx] = lo;
}

// ==================== kv prep: rms + RoPE -> bf16 hi/lo ====================
__global__ void kvprep(const float* __restrict__ kv, const float* __restrict__ w,
                       const float* __restrict__ freqs,
                       __nv_bfloat16* __restrict__ kvh, __nv_bfloat16* __restrict__ kvl)
{
    int s = blockIdx.x;
    const float* p = kv + (size_t)s * D_;
    int t = threadIdx.x;
    float v = p[t];
    float ss = v * v;
    __shared__ float red[8];
    __shared__ float rowbuf[D_];
    #pragma unroll
    for (int o = 16; o; o >>= 1) ss += __shfl_xor_sync(0xffffffffu, ss, o);
    if ((t & 31) == 0) red[t >> 5] = ss;
    __syncthreads();
    if (t < 32) {
        float r = (t < 8) ? red[t] : 0.f;
        #pragma unroll
        for (int o = 4; o; o >>= 1) r += __shfl_xor_sync(0xffffffffu, r, o);
        if (t == 0) red[0] = r;
    }
    __syncthreads();
    float inv = rsqrtf(red[0] / (float)D_ + EPS_);
    v = v * inv * w[t];
    rowbuf[t] = v;
    __syncthreads();
    float outv = v;
    if (t >= NOPE_) {
        int i = (t - NOPE_) >> 1;
        float f = freqs[s * RH_ + i];
        float c = cosf(f), sn = sinf(f);
        float x1 = rowbuf[NOPE_ + 2 * i], x2 = rowbuf[NOPE_ + 2 * i + 1];
        outv = ((t & 1) == 0) ? (x1 * c - x2 * sn) : (x1 * sn + x2 * c);
    }
    __nv_bfloat16 hi = __float2bfloat16(outv);
    __nv_bfloat16 lo = __float2bfloat16(outv - __bfloat162float(hi));
    kvh[(size_t)s * D_ + t] = hi;
    kvl[(size_t)s * D_ + t] = lo;
}

// ==================== WMMA flash attention, 64q x 64k tiles, 3-term bf16 split ===============
#define AQS 264   // bf16 k-stride for Q/KV tiles (256 + 8)
#define APS 72    // S fp32 / P bf16 stride
#define PVS 260   // PV fp32 stride (aliased over KV buffers)
// smem bytes: 4 * 64*AQS*2 (Qh,Ql,KVh,KVl) + 64*APS*4 (S ≡ Ph+Pl) + 3*64*4 (stats)
#define ATT_SMEM (4 * 64 * AQS * 2 + 64 * APS * 4 + 3 * 64 * 4)

__global__ void __launch_bounds__(256) attn_wmma(
    const __nv_bfloat16* __restrict__ qh, const __nv_bfloat16* __restrict__ ql,
    const __nv_bfloat16* __restrict__ kvh, const __nv_bfloat16* __restrict__ kvl,
    const float* __restrict__ sink, float* __restrict__ o)
{
    extern __shared__ char sm8[];
    __nv_bfloat16* Qh  = (__nv_bfloat16*)sm8;
    __nv_bfloat16* Ql  = Qh + 64 * AQS;
    __nv_bfloat16* KVh = Ql + 64 * AQS;
    __nv_bfloat16* KVl = KVh + 64 * AQS;
    float* PV = (float*)KVh;                   // alias: valid after KV MMAs done
    float* Sf = (float*)(KVl + 64 * AQS);      // stride APS fp32
    __nv_bfloat16* Ph = (__nv_bfloat16*)Sf;    // alias over S
    __nv_bfloat16* Pl = Ph + 64 * APS;
    float* rowm = Sf + 64 * APS;
    float* rowl = rowm + 64;
    float* rowa = rowm + 128;

    const int qb = (int)(gridDim.x - 1 - blockIdx.x);   // heavy first
    const int h  = blockIdx.y;
    const int s0 = qb * 64;
    const int tid = threadIdx.x;
    const int warp = tid >> 5;
    const int ty = tid >> 4, tx = tid & 15;

    // ---- load Q tile (bf16 hi/lo) ----
    {
        int r = tid >> 2, c0 = (tid & 3) * 64;
        const uint4* gh = (const uint4*)(qh + ((size_t)(s0 + r) * H_ + h) * D_ + c0);
        const uint4* gl = (const uint4*)(ql + ((size_t)(s0 + r) * H_ + h) * D_ + c0);
        #pragma unroll
        for (int j = 0; j < 8; j++) {
            *(uint4*)(Qh + r * AQS + c0 + j * 8) = gh[j];
            *(uint4*)(Ql + r * AQS + c0 + j * 8) = gl[j];
        }
    }
    if (tid < 64) { rowm[tid] = -1e30f; rowl[tid] = 0.f; }

    // o accumulator: rows ty*4+i, cols tx*4 + g*64
    float4 oa[4][4];
    #pragma unroll
    for (int i = 0; i < 4; i++)
        #pragma unroll
        for (int g = 0; g < 4; g++) oa[i][g] = make_float4(0.f, 0.f, 0.f, 0.f);

    const int wS_m = warp & 3, wS_n = warp >> 2;   // S phase: 4x2 warp grid
    const int wP_m = warp & 1, wP_n = warp >> 1;   // PV phase: 2x4 warp grid

    const int ntiles = qb + 1;
    for (int t0 = 0; t0 < ntiles; t0++) {
        __syncthreads();   // prior-tile PV reads done; KV/PV smem free
        // ---- load KV tile ----
        {
            int r = tid >> 2, c0 = (tid & 3) * 64;
            const uint4* gh = (const uint4*)(kvh + (size_t)(t0 * 64 + r) * D_ + c0);
            const uint4* gl = (const uint4*)(kvl + (size_t)(t0 * 64 + r) * D_ + c0);
            #pragma unroll
            for (int j = 0; j < 8; j++) {
                *(uint4*)(KVh + r * AQS + c0 + j * 8) = gh[j];
                *(uint4*)(KVl + r * AQS + c0 + j * 8) = gl[j];
            }
        }
        __syncthreads();

        // ---- S = Q * KV^T (3-term split) ----
        {
            wmma::fragment<wmma::accumulator, 16, 16, 16, float> sacc[2];
            #pragma unroll
            for (int j = 0; j < 2; j++) wmma::fill_fragment(sacc[j], 0.0f);
            #pragma unroll 2
            for (int ks = 0; ks < 16; ks++) {
                wmma::fragment<wmma::matrix_a, 16, 16, 16, __nv_bfloat16, wmma::row_major> ah, al;
                wmma::fragment<wmma::matrix_b, 16, 16, 16, __nv_bfloat16, wmma::col_major> bh[2], bl[2];
                wmma::load_matrix_sync(ah, Qh + (wS_m * 16) * AQS + ks * 16, AQS);
                wmma::load_matrix_sync(al, Ql + (wS_m * 16) * AQS + ks * 16, AQS);
                #pragma unroll
                for (int j = 0; j < 2; j++) {
                    wmma::load_matrix_sync(bh[j], KVh + (wS_n * 32 + j * 16) * AQS + ks * 16, AQS);
                    wmma::load_matrix_sync(bl[j], KVl + (wS_n * 32 + j * 16) * AQS + ks * 16, AQS);
                }
                #pragma unroll
                for (int j = 0; j < 2; j++) {
                    wmma::mma_sync(sacc[j], ah, bh[j], sacc[j]);
                    wmma::mma_sync(sacc[j], ah, bl[j], sacc[j]);
                    wmma::mma_sync(sacc[j], al, bh[j], sacc[j]);
                }
            }
            #pragma unroll
            for (int j = 0; j < 2; j++)
                wmma::store_matrix_sync(Sf + (wS_m * 16) * APS + wS_n * 32 + j * 16,
                                        sacc[j], APS, wmma::mem_row_major);
        }
        __syncthreads();

        // ---- online softmax (S in regs, then P hi/lo written over S) ----
        {
            int r = tid >> 2, sub = tid & 3;
            float vals[16];
            float mloc = -1e30f;
            #pragma unroll
            for (int tt = 0; tt < 16; tt++) {
                int c = sub * 16 + tt;
                float v = Sf[r * APS + c] * SCALE_;
                if (t0 * 64 + c > s0 + r) v = -1e30f;
                vals[tt] = v;
                mloc = fmaxf(mloc, v);
            }
            mloc = fmaxf(mloc, __shfl_xor_sync(0xffffffffu, mloc, 1));
            mloc = fmaxf(mloc, __shfl_xor_sync(0xffffffffu, mloc, 2));
            float mold = rowm[r];
            float mnew = fmaxf(mold, mloc);
            float psum = 0.f;
            float e[16];
            #pragma unroll
            for (int tt = 0; tt < 16; tt++) {
                e[tt] = __expf(vals[tt] - mnew);
                psum += e[tt];
            }
            psum += __shfl_xor_sync(0xffffffffu, psum, 1);
            psum += __shfl_xor_sync(0xffffffffu, psum, 2);
            if (sub == 0) {
                float alpha = __expf(mold - mnew);
                rowa[r] = alpha;
                rowl[r] = rowl[r] * alpha + psum;
                rowm[r] = mnew;
            }
            __syncthreads();   // all S reads complete before P overwrites the buffer
            #pragma unroll
            for (int tt = 0; tt < 16; tt++) {
                int c = sub * 16 + tt;
                __nv_bfloat16 hi = __float2bfloat16(e[tt]);
                Ph[r * APS + c] = hi;
                Pl[r * APS + c] = __float2bfloat16(e[tt] - __bfloat162float(hi));
            }
        }
        __syncthreads();

        // ---- PV = P * KV (3-term split) ----
        {
            wmma::fragment<wmma::accumulator, 16, 16, 16, float> pacc[2][4];
            #pragma unroll
            for (int i = 0; i < 2; i++)
                #pragma unroll
                for (int n = 0; n < 4; n++) wmma::fill_fragment(pacc[i][n], 0.0f);
            #pragma unroll
            for (int ks = 0; ks < 4; ks++) {
                wmma::fragment<wmma::matrix_a, 16, 16, 16, __nv_bfloat16, wmma::row_major> ph[2], pl[2];
                #pragma unroll
                for (int i = 0; i < 2; i++) {
                    wmma::load_matrix_sync(ph[i], Ph + (wP_m * 32 + i * 16) * APS + ks * 16, APS);
                    wmma::load_matrix_sync(pl[i], Pl + (wP_m * 32 + i * 16) * APS + ks * 16, APS);
                }
                #pragma unroll
                for (int n = 0; n < 4; n++) {
                    wmma::fragment<wmma::matrix_b, 16, 16, 16, __nv_bfloat16, wmma::row_major> bh, bl;
                    wmma::load_matrix_sync(bh, KVh + (ks * 16) * AQS + wP_n * 64 + n * 16, AQS);
                    wmma::load_matrix_sync(bl, KVl + (ks * 16) * AQS + wP_n * 64 + n * 16, AQS);
                    #pragma unroll
                    for (int i = 0; i < 2; i++) {
                        wmma::mma_sync(pacc[i][n], ph[i], bh, pacc[i][n]);
                        wmma::mma_sync(pacc[i][n], ph[i], bl, pacc[i][n]);
                        wmma::mma_sync(pacc[i][n], pl[i], bh, pacc[i][n]);
                    }
                }
            }
            __syncthreads();   // all KV fragment reads done before PV alias store
            #pragma unroll
            for (int i = 0; i < 2; i++)
                #pragma unroll
                for (int n = 0; n < 4; n++)
                    wmma::store_matrix_sync(PV + (wP_m * 32 + i * 16) * PVS + wP_n * 64 + n * 16,
                                            pacc[i][n], PVS, wmma::mem_row_major);
        }
        __syncthreads();

        // ---- o = o * alpha + PV ----
        {
            float al4[4];
            #pragma unroll
            for (int i = 0; i < 4; i++) al4[i] = rowa[ty * 4 + i];
            #pragma unroll
            for (int i = 0; i < 4; i++) {
                int r = ty * 4 + i;
                #pragma unroll
                for (int g = 0; g < 4; g++) {
                    float4 pv = *(const float4*)&PV[r * PVS + tx * 4 + g * 64];
                    oa[i][g].x = oa[i][g].x * al4[i] + pv.x;
                    oa[i][g].y = oa[i][g].y * al4[i] + pv.y;
                    oa[i][g].z = oa[i][g].z * al4[i] + pv.z;
                    oa[i][g].w = oa[i][g].w * al4[i] + pv.w;
                }
            }
        }
    }

    // ---- finalize ----
    float sk = sink[h];
    #pragma unroll
    for (int i = 0; i < 4; i++) {
        int r = ty * 4 + i;
        float denom = rowl[r] + __expf(sk - rowm[r]);
        float inv = 1.f / denom;
        float* op = o + ((size_t)(s0 + r) * H_ + h) * D_ + tx * 4;
        #pragma unroll
        for (int g = 0; g < 4; g++) {
            *(float4*)(op + g * 64) = make_float4(
                oa[i][g].x * inv, oa[i][g].y * inv, oa[i][g].z * inv, oa[i][g].w * inv);
        }
    }
}

// ==================== conjugate RoPE ====================
__global__ void o_rope_conj(float* __restrict__ o, const float* __restrict__ freqs)
{
    int s = blockIdx.x, h = blockIdx.y;
    int i = threadIdx.x;
    float* p = o + ((size_t)s * H_ + h) * D_ + NOPE_;
    float f = freqs[s * RH_ + i];
    float c = cosf(f), sn = sinf(f);
    float x1 = p[2 * i], x2 = p[2 * i + 1];
    p[2 * i]     = x1 * c + x2 * sn;
    p[2 * i + 1] = x2 * c - x1 * sn;
}

// ==================== launch ====================
extern "C" void kernel_launch(void* const* d_in, const int* in_sizes, int n_in,
                              void* d_out, int out_size)
{
    const float* x         = (const float*)d_in[0];
    const float* freqs     = (const float*)d_in[1];
    const float* wq_a      = (const float*)d_in[2];
    const float* q_norm_w  = (const float*)d_in[3];
    const float* wq_b      = (const float*)d_in[4];
    const float* wkv       = (const float*)d_in[5];
    const float* kv_norm_w = (const float*)d_in[6];
    const float* wo_a_w    = (const float*)d_in[7];
    const float* wo_b      = (const float*)d_in[8];
    const float* attn_sink = (const float*)d_in[9];
    float* out = (float*)d_out;

    float *qa, *qbuf, *kvbuf, *obuf, *orbuf;
    cudaGetSymbolAddress((void**)&qa,    g_qa);
    cudaGetSymbolAddress((void**)&qbuf,  g_q);
    cudaGetSymbolAddress((void**)&kvbuf, g_kv);
    cudaGetSymbolAddress((void**)&obuf,  g_o);
    cudaGetSymbolAddress((void**)&orbuf, g_or);

    __nv_bfloat16 *xh, *xl, *wqah, *wqal, *wqbh, *wqbl, *qah, *qal;
    __nv_bfloat16 *woah, *woal, *wobh, *wobl, *oh, *ol, *orh, *orl;
    __nv_bfloat16 *qhh, *qll, *kvh, *kvl;
    cudaGetSymbolAddress((void**)&xh, g_xh);     cudaGetSymbolAddress((void**)&xl, g_xl);
    cudaGetSymbolAddress((void**)&wqah, g_wqah); cudaGetSymbolAddress((void**)&wqal, g_wqal);
    cudaGetSymbolAddress((void**)&wqbh, g_wqbh); cudaGetSymbolAddress((void**)&wqbl, g_wqbl);
    cudaGetSymbolAddress((void**)&qah, g_qah);   cudaGetSymbolAddress((void**)&qal, g_qal);
    cudaGetSymbolAddress((void**)&woah, g_woah); cudaGetSymbolAddress((void**)&woal, g_woal);
    cudaGetSymbolAddress((void**)&wobh, g_wobh); cudaGetSymbolAddress((void**)&wobl, g_wobl);
    cudaGetSymbolAddress((void**)&oh, g_oh);     cudaGetSymbolAddress((void**)&ol, g_ol);
    cudaGetSymbolAddress((void**)&orh, g_orh);   cudaGetSymbolAddress((void**)&orl, g_orl);
    cudaGetSymbolAddress((void**)&qhh, g_qh);    cudaGetSymbolAddress((void**)&qll, g_ql2);
    cudaGetSymbolAddress((void**)&kvh, g_kvh);   cudaGetSymbolAddress((void**)&kvl, g_kvl);

    static int smem_set = 0;
    if (!smem_set) {
        cudaFuncSetAttribute(attn_wmma, cudaFuncAttributeMaxDynamicSharedMemorySize,
                             ATT_SMEM);
        cudaFuncSetAttribute(gemm_bfs, cudaFuncAttributeMaxDynamicSharedMemorySize,
                             GBF_SMEM);
        smem_set = 1;
    }

    dim3 blk(256);
    // ---- conversions (inputs + weights) ----
    cvt_hilo<<<(S_*HID_/4 + 255)/256, 256>>>(x,      xh,   xl,   S_*HID_/4);
    cvt_hilo<<<(QL_*HID_/4 + 255)/256, 256>>>(wq_a,  wqah, wqal, QL_*HID_/4);
    cvt_hilo<<<(H_*D_*QL_/4 + 255)/256, 256>>>(wq_b, wqbh, wqbl, H_*D_*QL_/4);
    cvt_hilo<<<(G_*OR_*1024/4 + 255)/256, 256>>>(wo_a_w, woah, woal, G_*OR_*1024/4);
    cvt_hilo<<<(HID_*G_*OR_/4 + 255)/256, 256>>>(wo_b, wobh, wobl, HID_*G_*OR_/4);

    // q_a = x @ wq_a^T   [2048,1024], K=2048
    gemm_bfs<<<dim3(16, 8, 1), blk, GBF_SMEM>>>(xh, xl, HID_, wqah, wqal, HID_,
                                                qa, QL_, HID_, 0, 0, 0);
    // kv_raw = x @ wkv^T [2048,256], K=2048 (fp32)
    gemm_abt<<<dim3(32, 4), blk>>>(x, HID_, wkv, HID_, kvbuf, D_, HID_);
    // rms(q_a) -> hi/lo
    rmsnorm_hilo<<<S_, 256>>>(qa, q_norm_w, qah, qal);
    // q = q_a @ wq_b^T   [2048,4096], K=1024
    gemm_bfs<<<dim3(16, 32, 1), blk, GBF_SMEM>>>(qah, qal, QL_, wqbh, wqbl, QL_,
                                                 qbuf, H_ * D_, QL_, 0, 0, 0);
    // kv: rms + rope -> bf16 hi/lo
    kvprep<<<S_, 256>>>(kvbuf, kv_norm_w, freqs, kvh, kvl);
    // q: head-norm + rope -> bf16 hi/lo
    qprep<<<dim3(S_, H_), 256>>>(qbuf, freqs, qhh, qll);
    // attention (WMMA)
    attn_wmma<<<dim3(S_ / 64, H_), blk, ATT_SMEM>>>(qhh, qll, kvh, kvl, attn_sink, obuf);
    // conj rope on o
    o_rope_conj<<<dim3(S_, H_), 32>>>(obuf, freqs);
    // o -> hi/lo
    cvt_hilo<<<((int)((size_t)S_*H_*D_/4) + 255)/256, 256>>>(obuf, oh, ol, (int)((size_t)S_*H_*D_/4));
    // grouped low-rank: z = 4 groups, [2048,512] each, K=1024
    gemm_bfs<<<dim3(16, 4, 4), blk, GBF_SMEM>>>(oh, ol, H_ * D_, woah, woal, 1024,
                                                orbuf, G_ * OR_, 1024,
                                                1024L, (long)OR_ * 1024L, (long)OR_);
    // o_r -> hi/lo
    cvt_hilo<<<(S_*G_*OR_/4 + 255)/256, 256>>>(orbuf, orh, orl, S_*G_*OR_/4);
    // out = o_r @ wo_b^T [2048,2048], K=2048
    gemm_bfs<<<dim3(16, 16, 1), blk, GBF_SMEM>>>(orh, orl, G_ * OR_, wobh, wobl, HID_,
                                                 out, HID_, G_ * OR_, 0, 0, 0);
}

// round 13
// speedup vs baseline: 8.8746x; 1.0547x over previous
#include <cuda_runtime.h>
#include <cuda_bf16.h>
#include <mma.h>
#include <math.h>
#include <stdint.h>

using namespace nvcuda;

#define S_    2048
#define HID_  2048
#define H_    16
#define D_    256
#define NOPE_ 192
#define RH_   32
#define QL_   1024
#define OR_   512
#define G_    4
#define EPS_  1e-6f
#define SCALE_ 0.0625f

// -------- fp32 scratch --------
__device__ float g_qa[S_ * QL_];
__device__ float g_q[(size_t)S_ * H_ * D_];
__device__ float g_kv[S_ * D_];
__device__ float g_or[S_ * G_ * OR_];

// -------- bf16 hi/lo scratch --------
__device__ __nv_bfloat16 g_xh[S_ * HID_],        g_xl[S_ * HID_];
__device__ __nv_bfloat16 g_wqah[QL_ * HID_],     g_wqal[QL_ * HID_];
__device__ __nv_bfloat16 g_wqbh[H_ * D_ * QL_],  g_wqbl[H_ * D_ * QL_];
__device__ __nv_bfloat16 g_qah[S_ * QL_],        g_qal[S_ * QL_];
__device__ __nv_bfloat16 g_woah[G_ * OR_ * 1024], g_woal[G_ * OR_ * 1024];
__device__ __nv_bfloat16 g_wobh[HID_ * G_ * OR_], g_wobl[HID_ * G_ * OR_];
__device__ __nv_bfloat16 g_oh[(size_t)S_ * H_ * D_], g_ol[(size_t)S_ * H_ * D_];
__device__ __nv_bfloat16 g_orh[S_ * G_ * OR_],   g_orl[S_ * G_ * OR_];
// attention bf16 operands
__device__ __nv_bfloat16 g_qh[(size_t)S_ * H_ * D_], g_ql2[(size_t)S_ * H_ * D_];
__device__ __nv_bfloat16 g_kvh[S_ * D_],         g_kvl[S_ * D_];

__device__ __forceinline__ uint32_t b2u(__nv_bfloat162 h) {
    return *reinterpret_cast<uint32_t*>(&h);
}

// ==================== fp32 -> (hi, lo) bf16 conversion ====================
__global__ void cvt_hilo(const float* __restrict__ in,
                         __nv_bfloat16* __restrict__ h,
                         __nv_bfloat16* __restrict__ l, int n4)
{
    int i = blockIdx.x * blockDim.x + threadIdx.x;
    if (i >= n4) return;
    float4 v = ((const float4*)in)[i];
    __nv_bfloat162 h01 = __floats2bfloat162_rn(v.x, v.y);
    __nv_bfloat162 h23 = __floats2bfloat162_rn(v.z, v.w);
    __nv_bfloat162 l01 = __floats2bfloat162_rn(
        v.x - __bfloat162float(__low2bfloat16(h01)),
        v.y - __bfloat162float(__high2bfloat16(h01)));
    __nv_bfloat162 l23 = __floats2bfloat162_rn(
        v.z - __bfloat162float(__low2bfloat16(h23)),
        v.w - __bfloat162float(__high2bfloat16(h23)));
    ((uint2*)h)[i] = make_uint2(b2u(h01), b2u(h23));
    ((uint2*)l)[i] = make_uint2(b2u(l01), b2u(l23));
}

// ==================== split-bf16 tensor GEMM ====================
#define BST 72
#define GBF_SMEM (4 * 128 * BST * 2)

__global__ void __launch_bounds__(256, 2) gemm_bfs(
    const __nv_bfloat16* __restrict__ Ah, const __nv_bfloat16* __restrict__ Al, int lda,
    const __nv_bfloat16* __restrict__ Bh, const __nv_bfloat16* __restrict__ Bl, int ldb,
    float* __restrict__ C, int ldc, int K,
    long sAz, long sBz, long sCz)
{
    extern __shared__ __nv_bfloat16 sb[];
    __nv_bfloat16* Ah_s = sb;
    __nv_bfloat16* Al_s = sb + 128 * BST;
    __nv_bfloat16* Bh_s = sb + 2 * 128 * BST;
    __nv_bfloat16* Bl_s = sb + 3 * 128 * BST;

    Ah += (size_t)blockIdx.z * sAz;  Al += (size_t)blockIdx.z * sAz;
    Bh += (size_t)blockIdx.z * sBz;  Bl += (size_t)blockIdx.z * sBz;
    C  += (size_t)blockIdx.z * sCz;

    const int tid = threadIdx.x;
    const int warp = tid >> 5;
    const int wm = warp & 1, wn = warp >> 1;

    wmma::fragment<wmma::accumulator, 16, 16, 16, float> acc[4][2];
    #pragma unroll
    for (int i = 0; i < 4; i++)
        #pragma unroll
        for (int j = 0; j < 2; j++)
            wmma::fill_fragment(acc[i][j], 0.0f);

    const int r  = tid >> 1;
    const int c0 = (tid & 1) * 32;
    const size_t aoff = (size_t)(blockIdx.x * 128 + r) * lda + c0;
    const size_t boff = (size_t)(blockIdx.y * 128 + r) * ldb + c0;
    const int sidx = r * BST + c0;

    const int nkc = K >> 6;
    for (int kc = 0; kc < nkc; kc++) {
        __syncthreads();
        {
            const uint4* gah = (const uint4*)(Ah + aoff + kc * 64);
            const uint4* gal = (const uint4*)(Al + aoff + kc * 64);
            const uint4* gbh = (const uint4*)(Bh + boff + kc * 64);
            const uint4* gbl = (const uint4*)(Bl + boff + kc * 64);
            #pragma unroll
            for (int j = 0; j < 4; j++) {
                *(uint4*)(Ah_s + sidx + j * 8) = gah[j];
                *(uint4*)(Al_s + sidx + j * 8) = gal[j];
                *(uint4*)(Bh_s + sidx + j * 8) = gbh[j];
                *(uint4*)(Bl_s + sidx + j * 8) = gbl[j];
            }
        }
        __syncthreads();

        #pragma unroll
        for (int ks = 0; ks < 4; ks++) {
            wmma::fragment<wmma::matrix_a, 16, 16, 16, __nv_bfloat16, wmma::row_major> ah[4];
            wmma::fragment<wmma::matrix_b, 16, 16, 16, __nv_bfloat16, wmma::col_major> bh[2];
            #pragma unroll
            for (int i = 0; i < 4; i++)
                wmma::load_matrix_sync(ah[i], Ah_s + (wm * 64 + i * 16) * BST + ks * 16, BST);
            #pragma unroll
            for (int j = 0; j < 2; j++)
                wmma::load_matrix_sync(bh[j], Bh_s + (wn * 32 + j * 16) * BST + ks * 16, BST);
            #pragma unroll
            for (int i = 0; i < 4; i++)
                #pragma unroll
                for (int j = 0; j < 2; j++)
                    wmma::mma_sync(acc[i][j], ah[i], bh[j], acc[i][j]);
            {
                wmma::fragment<wmma::matrix_b, 16, 16, 16, __nv_bfloat16, wmma::col_major> bl[2];
                #pragma unroll
                for (int j = 0; j < 2; j++)
                    wmma::load_matrix_sync(bl[j], Bl_s + (wn * 32 + j * 16) * BST + ks * 16, BST);
                #pragma unroll
                for (int i = 0; i < 4; i++)
                    #pragma unroll
                    for (int j = 0; j < 2; j++)
                        wmma::mma_sync(acc[i][j], ah[i], bl[j], acc[i][j]);
            }
            {
                wmma::fragment<wmma::matrix_a, 16, 16, 16, __nv_bfloat16, wmma::row_major> al[4];
                #pragma unroll
                for (int i = 0; i < 4; i++)
                    wmma::load_matrix_sync(al[i], Al_s + (wm * 64 + i * 16) * BST + ks * 16, BST);
                #pragma unroll
                for (int i = 0; i < 4; i++)
                    #pragma unroll
                    for (int j = 0; j < 2; j++)
                        wmma::mma_sync(acc[i][j], al[i], bh[j], acc[i][j]);
            }
        }
    }

    #pragma unroll
    for (int i = 0; i < 4; i++)
        #pragma unroll
        for (int j = 0; j < 2; j++) {
            float* Cp = C + (size_t)(blockIdx.x * 128 + wm * 64 + i * 16) * ldc
                          + blockIdx.y * 128 + wn * 32 + j * 16;
            wmma::store_matrix_sync(Cp, acc[i][j], ldc, wmma::mem_row_major);
        }
}

// ==================== small fp32 GEMM (64x64) for kv ====================
__global__ void __launch_bounds__(256) gemm_abt(
    const float* __restrict__ A, int lda,
    const float* __restrict__ B, int ldb,
    float* __restrict__ C, int ldc, int K)
{
    __shared__ float As[16][68];
    __shared__ float Bs[16][68];
    const int tid = threadIdx.x;
    const int tx = tid & 15, ty = tid >> 4;
    const int lr = tid >> 2, lq = tid & 3;
    const float* Ab = A + (size_t)(blockIdx.x * 64 + lr) * lda + lq * 4;
    const float* Bb = B + (size_t)(blockIdx.y * 64 + lr) * ldb + lq * 4;
    float acc[4][4] = {};
    for (int k0 = 0; k0 < K; k0 += 16) {
        float4 av = *(const float4*)(Ab + k0);
        float4 bv = *(const float4*)(Bb + k0);
        As[lq*4+0][lr] = av.x; As[lq*4+1][lr] = av.y;
        As[lq*4+2][lr] = av.z; As[lq*4+3][lr] = av.w;
        Bs[lq*4+0][lr] = bv.x; Bs[lq*4+1][lr] = bv.y;
        Bs[lq*4+2][lr] = bv.z; Bs[lq*4+3][lr] = bv.w;
        __syncthreads();
        #pragma unroll
        for (int k = 0; k < 16; k++) {
            float4 a = *(const float4*)&As[k][ty * 4];
            float4 b = *(const float4*)&Bs[k][tx * 4];
            float ar[4] = {a.x, a.y, a.z, a.w};
            float br[4] = {b.x, b.y, b.z, b.w};
            #pragma unroll
            for (int i = 0; i < 4; i++)
                #pragma unroll
                for (int j = 0; j < 4; j++)
                    acc[i][j] += ar[i] * br[j];
        }
        __syncthreads();
    }
    float* Cp = C + (size_t)(blockIdx.x * 64 + ty * 4) * ldc + blockIdx.y * 64 + tx * 4;
    #pragma unroll
    for (int i = 0; i < 4; i++) {
        float4 v = make_float4(acc[i][0], acc[i][1], acc[i][2], acc[i][3]);
        *(float4*)(Cp + (size_t)i * ldc) = v;
    }
}

// ==================== RMS norm (L=1024) emitting hi/lo bf16 ====================
__global__ void rmsnorm_hilo(const float* __restrict__ x, const float* __restrict__ w,
                             __nv_bfloat16* __restrict__ h, __nv_bfloat16* __restrict__ l)
{
    int row = blockIdx.x;
    int t = threadIdx.x;
    const float4* p = (const float4*)(x + (size_t)row * QL_);
    float4 v = p[t];
    float ss = v.x * v.x + v.y * v.y + v.z * v.z + v.w * v.w;
    __shared__ float red[8];
    #pragma unroll
    for (int o = 16; o; o >>= 1) ss += __shfl_xor_sync(0xffffffffu, ss, o);
    if ((t & 31) == 0) red[t >> 5] = ss;
    __syncthreads();
    if (t < 32) {
        float r = (t < 8) ? red[t] : 0.f;
        #pragma unroll
        for (int o = 4; o; o >>= 1) r += __shfl_xor_sync(0xffffffffu, r, o);
        if (t == 0) red[0] = r;
    }
    __syncthreads();
    float inv = rsqrtf(red[0] / (float)QL_ + EPS_);
    float4 wv = ((const float4*)w)[t];
    float4 o4 = make_float4(v.x * inv * wv.x, v.y * inv * wv.y,
                            v.z * inv * wv.z, v.w * inv * wv.w);
    __nv_bfloat162 h01 = __floats2bfloat162_rn(o4.x, o4.y);
    __nv_bfloat162 h23 = __floats2bfloat162_rn(o4.z, o4.w);
    __nv_bfloat162 l01 = __floats2bfloat162_rn(
        o4.x - __bfloat162float(__low2bfloat16(h01)),
        o4.y - __bfloat162float(__high2bfloat16(h01)));
    __nv_bfloat162 l23 = __floats2bfloat162_rn(
        o4.z - __bfloat162float(__low2bfloat16(h23)),
        o4.w - __bfloat162float(__high2bfloat16(h23)));
    ((uint2*)(h + (size_t)row * QL_))[t] = make_uint2(b2u(h01), b2u(h23));
    ((uint2*)(l + (size_t)row * QL_))[t] = make_uint2(b2u(l01), b2u(l23));
}

// ==================== q prep: head-norm + RoPE + pre-scale -> bf16 hi/lo ====================
__global__ void qprep(const float* __restrict__ q, const float* __restrict__ freqs,
                      __nv_bfloat16* __restrict__ qh, __nv_bfloat16* __restrict__ ql)
{
    int s = blockIdx.x, h = blockIdx.y;
    const float* p = q + ((size_t)s * H_ + h) * D_;
    int t = threadIdx.x;
    float v = p[t];
    float ss = v * v;
    __shared__ float red[8];
    __shared__ float rowbuf[D_];
    #pragma unroll
    for (int o = 16; o; o >>= 1) ss += __shfl_xor_sync(0xffffffffu, ss, o);
    if ((t & 31) == 0) red[t >> 5] = ss;
    __syncthreads();
    if (t < 32) {
        float r = (t < 8) ? red[t] : 0.f;
        #pragma unroll
        for (int o = 4; o; o >>= 1) r += __shfl_xor_sync(0xffffffffu, r, o);
        if (t == 0) red[0] = r;
    }
    __syncthreads();
    float inv = rsqrtf(red[0] / (float)D_ + EPS_);
    v *= inv;
    rowbuf[t] = v;
    __syncthreads();
    float outv = v;
    if (t >= NOPE_) {
        int i = (t - NOPE_) >> 1;
        float f = freqs[s * RH_ + i];
        float c = cosf(f), sn = sinf(f);
        float x1 = rowbuf[NOPE_ + 2 * i], x2 = rowbuf[NOPE_ + 2 * i + 1];
        outv = ((t & 1) == 0) ? (x1 * c - x2 * sn) : (x1 * sn + x2 * c);
    }
    outv *= SCALE_;   // fold score scale into Q
    __nv_bfloat16 hi = __float2bfloat16(outv);
    __nv_bfloat16 lo = __float2bfloat16(outv - __bfloat162float(hi));
    size_t idx = ((size_t)s * H_ + h) * D_ + t;
    qh[idx] = hi;
    ql[idx] = lo;
}

// ==================== kv prep: rms + RoPE -> bf16 hi/lo ====================
__global__ void kvprep(const float* __restrict__ kv, const float* __restrict__ w,
                       const float* __restrict__ freqs,
                       __nv_bfloat16* __restrict__ kvh, __nv_bfloat16* __restrict__ kvl)
{
    int s = blockIdx.x;
    const float* p = kv + (size_t)s * D_;
    int t = threadIdx.x;
    float v = p[t];
    float ss = v * v;
    __shared__ float red[8];
    __shared__ float rowbuf[D_];
    #pragma unroll
    for (int o = 16; o; o >>= 1) ss += __shfl_xor_sync(0xffffffffu, ss, o);
    if ((t & 31) == 0) red[t >> 5] = ss;
    __syncthreads();
    if (t < 32) {
        float r = (t < 8) ? red[t] : 0.f;
        #pragma unroll
        for (int o = 4; o; o >>= 1) r += __shfl_xor_sync(0xffffffffu, r, o);
        if (t == 0) red[0] = r;
    }
    __syncthreads();
    float inv = rsqrtf(red[0] / (float)D_ + EPS_);
    v = v * inv * w[t];
    rowbuf[t] = v;
    __syncthreads();
    float outv = v;
    if (t >= NOPE_) {
        int i = (t - NOPE_) >> 1;
        float f = freqs[s * RH_ + i];
        float c = cosf(f), sn = sinf(f);
        float x1 = rowbuf[NOPE_ + 2 * i], x2 = rowbuf[NOPE_ + 2 * i + 1];
        outv = ((t & 1) == 0) ? (x1 * c - x2 * sn) : (x1 * sn + x2 * c);
    }
    __nv_bfloat16 hi = __float2bfloat16(outv);
    __nv_bfloat16 lo = __float2bfloat16(outv - __bfloat162float(hi));
    kvh[(size_t)s * D_ + t] = hi;
    kvl[(size_t)s * D_ + t] = lo;
}

// ==================== WMMA flash attention, no-rescale (|s|<=16), fused epilogue ============
// Scores bounded: ||q_scaled|| = 1 * 16 * SCALE = 1; ||kv|| = 16 -> |s| <= 16, exp(s) <= 9e6.
#define AQS 264   // bf16 k-stride for Q/KV tiles
#define APS 72    // S fp32 / P bf16 stride
#define PVS 260   // epilogue PV fp32 stride (aliased over dead Q region)
#define ATT_SMEM (4 * 64 * AQS * 2 + 64 * APS * 4 + 64 * 4)

__global__ void __launch_bounds__(256) attn_wmma(
    const __nv_bfloat16* __restrict__ qh, const __nv_bfloat16* __restrict__ ql,
    const __nv_bfloat16* __restrict__ kvh, const __nv_bfloat16* __restrict__ kvl,
    const float* __restrict__ sink, const float* __restrict__ freqs,
    __nv_bfloat16* __restrict__ ohi, __nv_bfloat16* __restrict__ olo)
{
    extern __shared__ char sm8[];
    __nv_bfloat16* Qh  = (__nv_bfloat16*)sm8;
    __nv_bfloat16* Ql  = Qh + 64 * AQS;
    __nv_bfloat16* KVh = Ql + 64 * AQS;
    __nv_bfloat16* KVl = KVh + 64 * AQS;
    float* PVb = (float*)Qh;                   // epilogue alias over dead Q region (66.6KB<=67.5KB)
    float* Sf = (float*)(KVl + 64 * AQS);      // stride APS fp32
    __nv_bfloat16* Ph = (__nv_bfloat16*)Sf;    // alias over S
    __nv_bfloat16* Pl = Ph + 64 * APS;
    float* rowl = Sf + 64 * APS;

    const int qb = (int)(gridDim.x - 1 - blockIdx.x);   // heavy first
    const int h  = blockIdx.y;
    const int s0 = qb * 64;
    const int tid = threadIdx.x;
    const int warp = tid >> 5;
    const int ty = tid >> 4, tx = tid & 15;

    // ---- load Q tile (bf16 hi/lo, pre-scaled) ----
    {
        int r = tid >> 2, c0 = (tid & 3) * 64;
        const uint4* gh = (const uint4*)(qh + ((size_t)(s0 + r) * H_ + h) * D_ + c0);
        const uint4* gl = (const uint4*)(ql + ((size_t)(s0 + r) * H_ + h) * D_ + c0);
        #pragma unroll
        for (int j = 0; j < 8; j++) {
            *(uint4*)(Qh + r * AQS + c0 + j * 8) = gh[j];
            *(uint4*)(Ql + r * AQS + c0 + j * 8) = gl[j];
        }
    }
    if (tid < 64) rowl[tid] = 0.f;

    const int wS_m = warp & 3, wS_n = warp >> 2;   // S phase: 4x2 warp grid
    const int wP_m = warp & 1, wP_n = warp >> 1;   // PV phase: 2x4 warp grid

    // persistent PV accumulator fragments (rows wP_m*32+i*16, cols wP_n*64+n*16)
    wmma::fragment<wmma::accumulator, 16, 16, 16, float> pacc[2][4];
    #pragma unroll
    for (int i = 0; i < 2; i++)
        #pragma unroll
        for (int n = 0; n < 4; n++) wmma::fill_fragment(pacc[i][n], 0.0f);

    const int ntiles = qb + 1;
    for (int t0 = 0; t0 < ntiles; t0++) {
        __syncthreads();   // prior-tile PV fragment reads done; KV smem free
        // ---- load KV tile ----
        {
            int r = tid >> 2, c0 = (tid & 3) * 64;
            const uint4* gh = (const uint4*)(kvh + (size_t)(t0 * 64 + r) * D_ + c0);
            const uint4* gl = (const uint4*)(kvl + (size_t)(t0 * 64 + r) * D_ + c0);
            #pragma unroll
            for (int j = 0; j < 8; j++) {
                *(uint4*)(KVh + r * AQS + c0 + j * 8) = gh[j];
                *(uint4*)(KVl + r * AQS + c0 + j * 8) = gl[j];
            }
        }
        __syncthreads();

        // ---- S = Qs * KV^T (3-term split) ----
        {
            wmma::fragment<wmma::accumulator, 16, 16, 16, float> sacc[2];
            #pragma unroll
            for (int j = 0; j < 2; j++) wmma::fill_fragment(sacc[j], 0.0f);
            #pragma unroll 2
            for (int ks = 0; ks < 16; ks++) {
                wmma::fragment<wmma::matrix_a, 16, 16, 16, __nv_bfloat16, wmma::row_major> ah, al;
                wmma::fragment<wmma::matrix_b, 16, 16, 16, __nv_bfloat16, wmma::col_major> bh[2], bl[2];
                wmma::load_matrix_sync(ah, Qh + (wS_m * 16) * AQS + ks * 16, AQS);
                wmma::load_matrix_sync(al, Ql + (wS_m * 16) * AQS + ks * 16, AQS);
                #pragma unroll
                for (int j = 0; j < 2; j++) {
                    wmma::load_matrix_sync(bh[j], KVh + (wS_n * 32 + j * 16) * AQS + ks * 16, AQS);
                    wmma::load_matrix_sync(bl[j], KVl + (wS_n * 32 + j * 16) * AQS + ks * 16, AQS);
                }
                #pragma unroll
                for (int j = 0; j < 2; j++) {
                    wmma::mma_sync(sacc[j], ah, bh[j], sacc[j]);
                    wmma::mma_sync(sacc[j], ah, bl[j], sacc[j]);
                    wmma::mma_sync(sacc[j], al, bh[j], sacc[j]);
                }
            }
            #pragma unroll
            for (int j = 0; j < 2; j++)
                wmma::store_matrix_sync(Sf + (wS_m * 16) * APS + wS_n * 32 + j * 16,
                                        sacc[j], APS, wmma::mem_row_major);
        }
        __syncthreads();

        // ---- softmax numerator: P = exp(s) (no max shift; |s|<=16), accumulate l ----
        {
            int r = tid >> 2, sub = tid & 3;
            float e[16];
            float psum = 0.f;
            #pragma unroll
            for (int tt = 0; tt < 16; tt++) {
                int c = sub * 16 + tt;
                float v = Sf[r * APS + c];
                e[tt] = (t0 * 64 + c <= s0 + r) ? __expf(v) : 0.f;
                psum += e[tt];
            }
            psum += __shfl_xor_sync(0xffffffffu, psum, 1);
            psum += __shfl_xor_sync(0xffffffffu, psum, 2);
            if (sub == 0) rowl[r] += psum;
            __syncthreads();   // all S reads complete before P overwrites the buffer
            #pragma unroll
            for (int tt = 0; tt < 16; tt++) {
                int c = sub * 16 + tt;
                __nv_bfloat16 hi = __float2bfloat16(e[tt]);
                Ph[r * APS + c] = hi;
                Pl[r * APS + c] = __float2bfloat16(e[tt] - __bfloat162float(hi));
            }
        }
        __syncthreads();

        // ---- pacc += P * KV (3-term split, in-place accumulate; no smem roundtrip) ----
        #pragma unroll
        for (int ks = 0; ks < 4; ks++) {
            wmma::fragment<wmma::matrix_a, 16, 16, 16, __nv_bfloat16, wmma::row_major> ph[2], pl[2];
            #pragma unroll
            for (int i = 0; i < 2; i++) {
                wmma::load_matrix_sync(ph[i], Ph + (wP_m * 32 + i * 16) * APS + ks * 16, APS);
                wmma::load_matrix_sync(pl[i], Pl + (wP_m * 32 + i * 16) * APS + ks * 16, APS);
            }
            #pragma unroll
            for (int n = 0; n < 4; n++) {
                wmma::fragment<wmma::matrix_b, 16, 16, 16, __nv_bfloat16, wmma::row_major> bh, bl;
                wmma::load_matrix_sync(bh, KVh + (ks * 16) * AQS + wP_n * 64 + n * 16, AQS);
                wmma::load_matrix_sync(bl, KVl + (ks * 16) * AQS + wP_n * 64 + n * 16, AQS);
                #pragma unroll
                for (int i = 0; i < 2; i++) {
                    wmma::mma_sync(pacc[i][n], ph[i], bh, pacc[i][n]);
                    wmma::mma_sync(pacc[i][n], ph[i], bl, pacc[i][n]);
                    wmma::mma_sync(pacc[i][n], pl[i], bh, pacc[i][n]);
                }
            }
        }
    }

    // ---- epilogue: dump pacc over dead Q region (Q reads ended at last S-phase sync) ----
    #pragma unroll
    for (int i = 0; i < 2; i++)
        #pragma unroll
        for (int n = 0; n < 4; n++)
            wmma::store_matrix_sync(PVb + (wP_m * 32 + i * 16) * PVS + wP_n * 64 + n * 16,
                                    pacc[i][n], PVS, wmma::mem_row_major);
    __syncthreads();

    // ---- finalize: divide, conj-RoPE on last 64 dims, emit hi/lo bf16 ----
    float sk = __expf(sink[h]);   // exp(sink - 0)
    #pragma unroll
    for (int i = 0; i < 4; i++) {
        int r = ty * 4 + i;
        int s = s0 + r;
        float inv = 1.f / (rowl[r] + sk);
        #pragma unroll
        for (int g = 0; g < 4; g++) {
            float4 pv = *(const float4*)&PVb[r * PVS + tx * 4 + g * 64];
            float4 v = make_float4(pv.x * inv, pv.y * inv, pv.z * inv, pv.w * inv);
            if (g == 3) {   // cols 192 + tx*4 .. +3: two rope pairs (tx*2, tx*2+1)
                float f0 = freqs[s * RH_ + tx * 2];
                float f1 = freqs[s * RH_ + tx * 2 + 1];
                float c0 = cosf(f0), sn0 = sinf(f0);
                float c1 = cosf(f1), sn1 = sinf(f1);
                float x1 = v.x, x2 = v.y;
                v.x = x1 * c0 + x2 * sn0;
                v.y = x2 * c0 - x1 * sn0;
                float y1 = v.z, y2 = v.w;
                v.z = y1 * c1 + y2 * sn1;
                v.w = y2 * c1 - y1 * sn1;
            }
            __nv_bfloat162 h01 = __floats2bfloat162_rn(v.x, v.y);
            __nv_bfloat162 h23 = __floats2bfloat162_rn(v.z, v.w);
            __nv_bfloat162 l01 = __floats2bfloat162_rn(
                v.x - __bfloat162float(__low2bfloat16(h01)),
                v.y - __bfloat162float(__high2bfloat16(h01)));
            __nv_bfloat162 l23 = __floats2bfloat162_rn(
                v.z - __bfloat162float(__low2bfloat16(h23)),
                v.w - __bfloat162float(__high2bfloat16(h23)));
            size_t oidx = ((size_t)s * H_ + h) * D_ + tx * 4 + g * 64;
            *(uint2*)(ohi + oidx) = make_uint2(b2u(h01), b2u(h23));
            *(uint2*)(olo + oidx) = make_uint2(b2u(l01), b2u(l23));
        }
    }
}

// ==================== launch ====================
extern "C" void kernel_launch(void* const* d_in, const int* in_sizes, int n_in,
                              void* d_out, int out_size)
{
    const float* x         = (const float*)d_in[0];
    const float* freqs     = (const float*)d_in[1];
    const float* wq_a      = (const float*)d_in[2];
    const float* q_norm_w  = (const float*)d_in[3];
    const float* wq_b      = (const float*)d_in[4];
    const float* wkv       = (const float*)d_in[5];
    const float* kv_norm_w = (const float*)d_in[6];
    const float* wo_a_w    = (const float*)d_in[7];
    const float* wo_b      = (const float*)d_in[8];
    const float* attn_sink = (const float*)d_in[9];
    float* out = (float*)d_out;

    float *qa, *qbuf, *kvbuf, *orbuf;
    cudaGetSymbolAddress((void**)&qa,    g_qa);
    cudaGetSymbolAddress((void**)&qbuf,  g_q);
    cudaGetSymbolAddress((void**)&kvbuf, g_kv);
    cudaGetSymbolAddress((void**)&orbuf, g_or);

    __nv_bfloat16 *xh, *xl, *wqah, *wqal, *wqbh, *wqbl, *qah, *qal;
    __nv_bfloat16 *woah, *woal, *wobh, *wobl, *oh, *ol, *orh, *orl;
    __nv_bfloat16 *qhh, *qll, *kvh, *kvl;
    cudaGetSymbolAddress((void**)&xh, g_xh);     cudaGetSymbolAddress((void**)&xl, g_xl);
    cudaGetSymbolAddress((void**)&wqah, g_wqah); cudaGetSymbolAddress((void**)&wqal, g_wqal);
    cudaGetSymbolAddress((void**)&wqbh, g_wqbh); cudaGetSymbolAddress((void**)&wqbl, g_wqbl);
    cudaGetSymbolAddress((void**)&qah, g_qah);   cudaGetSymbolAddress((void**)&qal, g_qal);
    cudaGetSymbolAddress((void**)&woah, g_woah); cudaGetSymbolAddress((void**)&woal, g_woal);
    cudaGetSymbolAddress((void**)&wobh, g_wobh); cudaGetSymbolAddress((void**)&wobl, g_wobl);
    cudaGetSymbolAddress((void**)&oh, g_oh);     cudaGetSymbolAddress((void**)&ol, g_ol);
    cudaGetSymbolAddress((void**)&orh, g_orh);   cudaGetSymbolAddress((void**)&orl, g_orl);
    cudaGetSymbolAddress((void**)&qhh, g_qh);    cudaGetSymbolAddress((void**)&qll, g_ql2);
    cudaGetSymbolAddress((void**)&kvh, g_kvh);   cudaGetSymbolAddress((void**)&kvl, g_kvl);

    static int smem_set = 0;
    if (!smem_set) {
        cudaFuncSetAttribute(attn_wmma, cudaFuncAttributeMaxDynamicSharedMemorySize,
                             ATT_SMEM);
        cudaFuncSetAttribute(gemm_bfs, cudaFuncAttributeMaxDynamicSharedMemorySize,
                             GBF_SMEM);
        smem_set = 1;
    }

    dim3 blk(256);
    // ---- conversions (inputs + weights) ----
    cvt_hilo<<<(S_*HID_/4 + 255)/256, 256>>>(x,      xh,   xl,   S_*HID_/4);
    cvt_hilo<<<(QL_*HID_/4 + 255)/256, 256>>>(wq_a,  wqah, wqal, QL_*HID_/4);
    cvt_hilo<<<(H_*D_*QL_/4 + 255)/256, 256>>>(wq_b, wqbh, wqbl, H_*D_*QL_/4);
    cvt_hilo<<<(G_*OR_*1024/4 + 255)/256, 256>>>(wo_a_w, woah, woal, G_*OR_*1024/4);
    cvt_hilo<<<(HID_*G_*OR_/4 + 255)/256, 256>>>(wo_b, wobh, wobl, HID_*G_*OR_/4);

    // q_a = x @ wq_a^T   [2048,1024], K=2048
    gemm_bfs<<<dim3(16, 8, 1), blk, GBF_SMEM>>>(xh, xl, HID_, wqah, wqal, HID_,
                                                qa, QL_, HID_, 0, 0, 0);
    // kv_raw = x @ wkv^T [2048,256], K=2048 (fp32)
    gemm_abt<<<dim3(32, 4), blk>>>(x, HID_, wkv, HID_, kvbuf, D_, HID_);
    // rms(q_a) -> hi/lo
    rmsnorm_hilo<<<S_, 256>>>(qa, q_norm_w, qah, qal);
    // q = q_a @ wq_b^T   [2048,4096], K=1024
    gemm_bfs<<<dim3(16, 32, 1), blk, GBF_SMEM>>>(qah, qal, QL_, wqbh, wqbl, QL_,
                                                 qbuf, H_ * D_, QL_, 0, 0, 0);
    // kv: rms + rope -> bf16 hi/lo
    kvprep<<<S_, 256>>>(kvbuf, kv_norm_w, freqs, kvh, kvl);
    // q: head-norm + rope + scale -> bf16 hi/lo
    qprep<<<dim3(S_, H_), 256>>>(qbuf, freqs, qhh, qll);
    // attention (WMMA, no-rescale) -> o hi/lo with fused conj-RoPE
    attn_wmma<<<dim3(S_ / 64, H_), blk, ATT_SMEM>>>(qhh, qll, kvh, kvl,
                                                    attn_sink, freqs, oh, ol);
    // grouped low-rank: z = 4 groups, [2048,512] each, K=1024
    gemm_bfs<<<dim3(16, 4, 4), blk, GBF_SMEM>>>(oh, ol, H_ * D_, woah, woal, 1024,
                                                orbuf, G_ * OR_, 1024,
                                                1024L, (long)OR_ * 1024L, (long)OR_);
    // o_r -> hi/lo
    cvt_hilo<<<(S_*G_*OR_/4 + 255)/256, 256>>>(orbuf, orh, orl, S_*G_*OR_/4);
    // out = o_r @ wo_b^T [2048,2048], K=2048
    gemm_bfs<<<dim3(16, 16, 1), blk, GBF_SMEM>>>(orh, orl, G_ * OR_, wobh, wobl, HID_,
                                                 out, HID_, G_ * OR_, 0, 0, 0);
}